// round 6
// baseline (speedup 1.0000x reference)
#include <cuda_runtime.h>
#include <stdint.h>

#define NSAMP 150
#define D_IN  784
#define D_H   512
#define D_OUT 10
#define BATCH 64

// ---------------- device scratch: activations (tf32 hi/lo pairs) ----------------
__device__ __align__(16) float g_Xh [BATCH * D_IN];
__device__ __align__(16) float g_Xl [BATCH * D_IN];
__device__ __align__(16) float g_H1h[NSAMP * BATCH * D_H];
__device__ __align__(16) float g_H1l[NSAMP * BATCH * D_H];
__device__ __align__(16) float g_H2h[NSAMP * BATCH * D_H];
__device__ __align__(16) float g_H2l[NSAMP * BATCH * D_H];
__device__ __align__(16) float g_H3 [NSAMP * BATCH * D_H];

// ---------------- tf32 helpers ----------------
__device__ __forceinline__ void tf32_split(float a, float& hi, float& lo) {
    uint32_t h, l;
    asm("cvt.rna.tf32.f32 %0, %1;" : "=r"(h) : "f"(a));
    float lf = a - __uint_as_float(h);
    asm("cvt.rna.tf32.f32 %0, %1;" : "=r"(l) : "f"(lf));
    hi = __uint_as_float(h); lo = __uint_as_float(l);
}
__device__ __forceinline__ void mma_tf32(float* c,
                                         float a0, float a1, float a2, float a3,
                                         float b0, float b1) {
    asm("mma.sync.aligned.m16n8k8.row.col.f32.tf32.tf32.f32 "
        "{%0,%1,%2,%3}, {%4,%5,%6,%7}, {%8,%9}, {%0,%1,%2,%3};"
        : "+f"(c[0]), "+f"(c[1]), "+f"(c[2]), "+f"(c[3])
        : "r"(__float_as_uint(a0)), "r"(__float_as_uint(a1)),
          "r"(__float_as_uint(a2)), "r"(__float_as_uint(a3)),
          "r"(__float_as_uint(b0)), "r"(__float_as_uint(b1)));
}

// ---------------- threefry2x32 (20 rounds), bit-exact vs jax._src.prng ----------------
__device__ __forceinline__ void tf_round(uint32_t& x0, uint32_t& x1, int r) {
    x0 += x1;
    x1 = __funnelshift_l(x1, x1, r);
    x1 ^= x0;
}
__device__ __forceinline__ uint2 threefry2x32_dev(uint32_t k0, uint32_t k1,
                                                  uint32_t x0, uint32_t x1) {
    uint32_t k2 = k0 ^ k1 ^ 0x1BD11BDAu;
    x0 += k0; x1 += k1;
    tf_round(x0,x1,13); tf_round(x0,x1,15); tf_round(x0,x1,26); tf_round(x0,x1,6);
    x0 += k1; x1 += k2 + 1u;
    tf_round(x0,x1,17); tf_round(x0,x1,29); tf_round(x0,x1,16); tf_round(x0,x1,24);
    x0 += k2; x1 += k0 + 2u;
    tf_round(x0,x1,13); tf_round(x0,x1,15); tf_round(x0,x1,26); tf_round(x0,x1,6);
    x0 += k0; x1 += k1 + 3u;
    tf_round(x0,x1,17); tf_round(x0,x1,29); tf_round(x0,x1,16); tf_round(x0,x1,24);
    x0 += k1; x1 += k2 + 4u;
    tf_round(x0,x1,13); tf_round(x0,x1,15); tf_round(x0,x1,26); tf_round(x0,x1,6);
    x0 += k2; x1 += k0 + 5u;
    return make_uint2(x0, x1);
}

// ---------------- bits -> N(0,1): fast-math clone of XLA pipeline ----------------
__device__ __forceinline__ float jax_normal_fast(uint32_t bits) {
    const float LO = -0.99999994039535522461f;
    float f = __uint_as_float((bits >> 9) | 0x3f800000u) - 1.0f;
    float x = fmaxf(__fmaf_rn(f, 2.0f, LO), LO);
    float y = x * x;
    float t = 1.0f - y;
    float w = (t == 1.0f) ? y : -__logf(t);
    float p;
    if (w < 5.0f) {
        float ww = w - 2.5f;
        p =                2.81022636e-08f;
        p = __fmaf_rn(p, ww, 3.43273939e-07f);
        p = __fmaf_rn(p, ww, -3.5233877e-06f);
        p = __fmaf_rn(p, ww, -4.39150654e-06f);
        p = __fmaf_rn(p, ww, 0.00021858087f);
        p = __fmaf_rn(p, ww, -0.00125372503f);
        p = __fmaf_rn(p, ww, -0.00417768164f);
        p = __fmaf_rn(p, ww, 0.246640727f);
        p = __fmaf_rn(p, ww, 1.50140941f);
    } else {
        float ww = __fsqrt_rn(w) - 3.0f;
        p =                -0.000200214257f;
        p = __fmaf_rn(p, ww, 0.000100950558f);
        p = __fmaf_rn(p, ww, 0.00134934322f);
        p = __fmaf_rn(p, ww, -0.00367342844f);
        p = __fmaf_rn(p, ww, 0.00573950773f);
        p = __fmaf_rn(p, ww, -0.0076224613f);
        p = __fmaf_rn(p, ww, 0.00943887047f);
        p = __fmaf_rn(p, ww, 1.00167406f);
        p = __fmaf_rn(p, ww, 2.83297682f);
    }
    return 1.4142135623730951f * (p * x);
}

// ---------------- tiny pre-kernel: split x into tf32 hi/lo ----------------
__global__ void split_x(const float* __restrict__ x,
                        float* __restrict__ xh, float* __restrict__ xl, int n) {
    int i = blockIdx.x * blockDim.x + threadIdx.x;
    if (i < n) {
        float h, l;
        tf32_split(x[i], h, l);
        xh[i] = h; xl[i] = l;
    }
}

// ---------------- fused layer: gen (pre-split) + tf32 MMA, 1 barrier/chunk ----------------
// inputs as hi/lo pairs; output hi/lo pairs if SPLIT_OUT, else plain floats to Ch.
__global__ __launch_bounds__(256, 2) void fused_layer(
    const float* __restrict__ Ah, const float* __restrict__ Al, long long strideA,
    const float* __restrict__ muW, const float* __restrict__ vW,
    const float* __restrict__ mub, const float* __restrict__ vb,
    float* __restrict__ Ch, float* __restrict__ Cl,
    int K, int N, int relu, int split_out,
    uint32_t wk0, uint32_t wk1, uint32_t bk0, uint32_t bk1)
{
    const int s    = blockIdx.y;
    const int nblk = blockIdx.x;
    const int t    = threadIdx.x;      // 256

    __shared__ float Ash[2][16][68];
    __shared__ float Asl[2][16][68];
    __shared__ float Bsh[2][16][68];
    __shared__ float Bsl[2][16][68];
    __shared__ float bias_s[64];

    const int lr   = t >> 2;           // 0..63 row (producer)
    const int lk4  = (t & 3) << 2;     // k offset 0,4,8,12
    const int lane = t & 31;
    const int wrp  = t >> 5;           // 0..7
    const int m0   = (wrp & 3) * 16;
    const int n0b  = (wrp >> 2) * 32;
    const int ka   = lane & 3;
    const int ra   = lane >> 2;

    const float* Abh = Ah + (long long)s * strideA;
    const float* Abl = Al + (long long)s * strideA;
    const int    n_glob = nblk * 64 + lr;
    const float* muRow  = muW + (long long)n_glob * K;
    const float* vRow   = vW  + (long long)n_glob * K;
    const uint32_t eBase = ((uint32_t)s * (uint32_t)N + (uint32_t)n_glob) * (uint32_t)K;

    if (t < 64) {
        int nb = nblk * 64 + t;
        uint2 r = threefry2x32_dev(bk0, bk1, 0u, (uint32_t)(s * N + nb));
        bias_s[t] = __fmaf_rn(__expf(vb[nb]), jax_normal_fast(r.x ^ r.y), mub[nb]);
    }

    // ---- prologue: load + gen chunk 0 into registers ----
    float4 avh = *(const float4*)(Abh + (long long)lr * K + lk4);
    float4 avl = *(const float4*)(Abl + (long long)lr * K + lk4);
    float4 mv  = *(const float4*)(muRow + lk4);
    float4 vv  = *(const float4*)(vRow  + lk4);
    float wh[4], wl[4];
    {
        uint32_t e0 = eBase + lk4;
        uint2 r0 = threefry2x32_dev(wk0, wk1, 0u, e0 + 0);
        uint2 r1 = threefry2x32_dev(wk0, wk1, 0u, e0 + 1);
        uint2 r2 = threefry2x32_dev(wk0, wk1, 0u, e0 + 2);
        uint2 r3 = threefry2x32_dev(wk0, wk1, 0u, e0 + 3);
        tf32_split(__fmaf_rn(__expf(vv.x), jax_normal_fast(r0.x ^ r0.y), mv.x), wh[0], wl[0]);
        tf32_split(__fmaf_rn(__expf(vv.y), jax_normal_fast(r1.x ^ r1.y), mv.y), wh[1], wl[1]);
        tf32_split(__fmaf_rn(__expf(vv.z), jax_normal_fast(r2.x ^ r2.y), mv.z), wh[2], wl[2]);
        tf32_split(__fmaf_rn(__expf(vv.w), jax_normal_fast(r3.x ^ r3.y), mv.w), wh[3], wl[3]);
    }

    float acc[4][4];
#pragma unroll
    for (int i = 0; i < 4; i++)
#pragma unroll
        for (int j = 0; j < 4; j++) acc[i][j] = 0.0f;

    const int nch = K >> 4;

    // ---- main loop: store(c) | sync | gen(c+1) | MMA(c) -- single barrier ----
    for (int c = 0; c < nch; c++) {
        const int buf = c & 1;
        Ash[buf][lk4+0][lr] = avh.x; Ash[buf][lk4+1][lr] = avh.y;
        Ash[buf][lk4+2][lr] = avh.z; Ash[buf][lk4+3][lr] = avh.w;
        Asl[buf][lk4+0][lr] = avl.x; Asl[buf][lk4+1][lr] = avl.y;
        Asl[buf][lk4+2][lr] = avl.z; Asl[buf][lk4+3][lr] = avl.w;
        Bsh[buf][lk4+0][lr] = wh[0]; Bsh[buf][lk4+1][lr] = wh[1];
        Bsh[buf][lk4+2][lr] = wh[2]; Bsh[buf][lk4+3][lr] = wh[3];
        Bsl[buf][lk4+0][lr] = wl[0]; Bsl[buf][lk4+1][lr] = wl[1];
        Bsl[buf][lk4+2][lr] = wl[2]; Bsl[buf][lk4+3][lr] = wl[3];
        __syncthreads();

        if (c + 1 < nch) {
            const int k0n = (c + 1) << 4;
            avh = *(const float4*)(Abh + (long long)lr * K + k0n + lk4);
            avl = *(const float4*)(Abl + (long long)lr * K + k0n + lk4);
            mv  = *(const float4*)(muRow + k0n + lk4);
            vv  = *(const float4*)(vRow  + k0n + lk4);
            uint32_t e0 = eBase + (uint32_t)(k0n + lk4);
            uint2 r0 = threefry2x32_dev(wk0, wk1, 0u, e0 + 0);
            uint2 r1 = threefry2x32_dev(wk0, wk1, 0u, e0 + 1);
            uint2 r2 = threefry2x32_dev(wk0, wk1, 0u, e0 + 2);
            uint2 r3 = threefry2x32_dev(wk0, wk1, 0u, e0 + 3);
            tf32_split(__fmaf_rn(__expf(vv.x), jax_normal_fast(r0.x ^ r0.y), mv.x), wh[0], wl[0]);
            tf32_split(__fmaf_rn(__expf(vv.y), jax_normal_fast(r1.x ^ r1.y), mv.y), wh[1], wl[1]);
            tf32_split(__fmaf_rn(__expf(vv.z), jax_normal_fast(r2.x ^ r2.y), mv.z), wh[2], wl[2]);
            tf32_split(__fmaf_rn(__expf(vv.w), jax_normal_fast(r3.x ^ r3.y), mv.w), wh[3], wl[3]);
        }

        // consumer: pure LDS + MMA (3xTF32 from pre-split operands)
#pragma unroll
        for (int ks = 0; ks < 2; ks++) {
            const int kb = ks * 8;
            float a0h = Ash[buf][kb + ka    ][m0 + ra    ];
            float a1h = Ash[buf][kb + ka    ][m0 + ra + 8];
            float a2h = Ash[buf][kb + ka + 4][m0 + ra    ];
            float a3h = Ash[buf][kb + ka + 4][m0 + ra + 8];
            float a0l = Asl[buf][kb + ka    ][m0 + ra    ];
            float a1l = Asl[buf][kb + ka    ][m0 + ra + 8];
            float a2l = Asl[buf][kb + ka + 4][m0 + ra    ];
            float a3l = Asl[buf][kb + ka + 4][m0 + ra + 8];
#pragma unroll
            for (int tj = 0; tj < 4; tj++) {
                float bh0 = Bsh[buf][kb + ka    ][n0b + tj * 8 + ra];
                float bh1 = Bsh[buf][kb + ka + 4][n0b + tj * 8 + ra];
                float bl0 = Bsl[buf][kb + ka    ][n0b + tj * 8 + ra];
                float bl1 = Bsl[buf][kb + ka + 4][n0b + tj * 8 + ra];
                mma_tf32(acc[tj], a0l, a1l, a2l, a3l, bh0, bh1);  // alo*bhi
                mma_tf32(acc[tj], a0h, a1h, a2h, a3h, bl0, bl1);  // ahi*blo
                mma_tf32(acc[tj], a0h, a1h, a2h, a3h, bh0, bh1);  // ahi*bhi
            }
        }
    }

    // ---- epilogue: +bias, relu, (split) store ----
    const int row0 = m0 + ra;
    const int row1 = m0 + ra + 8;
#pragma unroll
    for (int tj = 0; tj < 4; tj++) {
        int n = n0b + tj * 8 + 2 * ka;
        float bb0 = bias_s[n], bb1 = bias_s[n + 1];
        float v00 = acc[tj][0] + bb0, v01 = acc[tj][1] + bb1;
        float v10 = acc[tj][2] + bb0, v11 = acc[tj][3] + bb1;
        if (relu) {
            v00 = fmaxf(v00, 0.f); v01 = fmaxf(v01, 0.f);
            v10 = fmaxf(v10, 0.f); v11 = fmaxf(v11, 0.f);
        }
        long long o0 = ((long long)s * 64 + row0) * N + nblk * 64 + n;
        long long o1 = ((long long)s * 64 + row1) * N + nblk * 64 + n;
        if (split_out) {
            float h, l;
            float2 h0, l0, h1, l1;
            tf32_split(v00, h, l); h0.x = h; l0.x = l;
            tf32_split(v01, h, l); h0.y = h; l0.y = l;
            tf32_split(v10, h, l); h1.x = h; l1.x = l;
            tf32_split(v11, h, l); h1.y = h; l1.y = l;
            *(float2*)(Ch + o0) = h0; *(float2*)(Cl + o0) = l0;
            *(float2*)(Ch + o1) = h1; *(float2*)(Cl + o1) = l1;
        } else {
            *(float2*)(Ch + o0) = make_float2(v00, v01);
            *(float2*)(Ch + o1) = make_float2(v10, v11);
        }
    }
}

// ---------------- final layer: 2 blocks/sample, gen partitioned by output-half ----------
__global__ __launch_bounds__(256) void layer3_fused(
    const float* __restrict__ H,
    const float* __restrict__ muW, const float* __restrict__ vW,
    const float* __restrict__ mub, const float* __restrict__ vb,
    float* __restrict__ out,
    uint32_t wk0, uint32_t wk1, uint32_t bk0, uint32_t bk1)
{
    const int s = blockIdx.x;
    const int h = blockIdx.y;
    const int t = threadIdx.x;
    __shared__ float Ws[5 * D_H];
    __shared__ float bsm[5];

#pragma unroll
    for (int i = 0; i < (5 * D_H) / 256; i++) {
        int j = t + 256 * i;
        uint32_t e = (uint32_t)(s * (D_OUT * D_H) + h * (5 * D_H) + j);
        uint2 r = threefry2x32_dev(wk0, wk1, 0u, e);
        int jg = h * (5 * D_H) + j;
        Ws[j] = __fmaf_rn(__expf(vW[jg]), jax_normal_fast(r.x ^ r.y), muW[jg]);
    }
    if (t < 5) {
        int og = h * 5 + t;
        uint2 r = threefry2x32_dev(bk0, bk1, 0u, (uint32_t)(s * D_OUT + og));
        bsm[t] = __fmaf_rn(__expf(vb[og]), jax_normal_fast(r.x ^ r.y), mub[og]);
    }
    __syncthreads();

    const int w = t >> 5, l = t & 31;
#pragma unroll
    for (int ri = 0; ri < 8; ri++) {
        int b = w * 8 + ri;
        const float* Hb = H + ((long long)s * BATCH + b) * D_H;
        float hh[16];
#pragma unroll
        for (int i = 0; i < 16; i++) hh[i] = Hb[l + 32 * i];
#pragma unroll
        for (int o = 0; o < 5; o++) {
            float acc = 0.0f;
#pragma unroll
            for (int i = 0; i < 16; i++)
                acc = __fmaf_rn(hh[i], Ws[o * D_H + l + 32 * i], acc);
            acc += __shfl_xor_sync(0xffffffffu, acc, 16);
            acc += __shfl_xor_sync(0xffffffffu, acc, 8);
            acc += __shfl_xor_sync(0xffffffffu, acc, 4);
            acc += __shfl_xor_sync(0xffffffffu, acc, 2);
            acc += __shfl_xor_sync(0xffffffffu, acc, 1);
            if (l == 0)
                out[((long long)s * BATCH + b) * D_OUT + h * 5 + o] = acc + bsm[o];
        }
    }
}

// ---------------- host-side threefry (subkey derivation) ----------------
static inline uint32_t h_rotl(uint32_t x, int r) { return (x << r) | (x >> (32 - r)); }
static void tf_host(uint32_t k0, uint32_t k1, uint32_t x0, uint32_t x1,
                    uint32_t* o0, uint32_t* o1) {
    uint32_t k2 = k0 ^ k1 ^ 0x1BD11BDAu;
    x0 += k0; x1 += k1;
    static const int R[2][4] = {{13,15,26,6},{17,29,16,24}};
    const uint32_t ks[3] = {k0, k1, k2};
    for (int i = 0; i < 5; i++) {
        for (int r = 0; r < 4; r++) {
            x0 += x1; x1 = h_rotl(x1, R[i & 1][r]); x1 ^= x0;
        }
        x0 += ks[(i + 1) % 3];
        x1 += ks[(i + 2) % 3] + (uint32_t)(i + 1);
    }
    *o0 = x0; *o1 = x1;
}

extern "C" void kernel_launch(void* const* d_in, const int* in_sizes, int n_in,
                              void* d_out, int out_size) {
    const float* x    = (const float*)d_in[0];
    const float* muW0 = (const float*)d_in[1];
    const float* mub0 = (const float*)d_in[2];
    const float* muW1 = (const float*)d_in[3];
    const float* mub1 = (const float*)d_in[4];
    const float* muW2 = (const float*)d_in[5];
    const float* mub2 = (const float*)d_in[6];
    const float* muW3 = (const float*)d_in[7];
    const float* mub3 = (const float*)d_in[8];
    const float* vW0  = (const float*)d_in[9];
    const float* vb0  = (const float*)d_in[10];
    const float* vW1  = (const float*)d_in[11];
    const float* vb1  = (const float*)d_in[12];
    const float* vW2  = (const float*)d_in[13];
    const float* vb2  = (const float*)d_in[14];
    const float* vW3  = (const float*)d_in[15];
    const float* vb3  = (const float*)d_in[16];
    float* out = (float*)d_out;

    uint32_t kk[8][2];
    for (int i = 0; i < 8; i++) tf_host(0u, 1u, 0u, (uint32_t)i, &kk[i][0], &kk[i][1]);

    float *pXh, *pXl, *pH1h, *pH1l, *pH2h, *pH2l, *pH3;
    cudaGetSymbolAddress((void**)&pXh,  g_Xh);
    cudaGetSymbolAddress((void**)&pXl,  g_Xl);
    cudaGetSymbolAddress((void**)&pH1h, g_H1h);
    cudaGetSymbolAddress((void**)&pH1l, g_H1l);
    cudaGetSymbolAddress((void**)&pH2h, g_H2h);
    cudaGetSymbolAddress((void**)&pH2l, g_H2l);
    cudaGetSymbolAddress((void**)&pH3,  g_H3);

    split_x<<<(BATCH * D_IN + 255) / 256, 256>>>(x, pXh, pXl, BATCH * D_IN);

    fused_layer<<<dim3(D_H/64, NSAMP), 256>>>(pXh, pXl, 0,
                                              muW0, vW0, mub0, vb0,
                                              pH1h, pH1l, D_IN, D_H, 1, 1,
                                              kk[0][0], kk[0][1], kk[1][0], kk[1][1]);
    fused_layer<<<dim3(D_H/64, NSAMP), 256>>>(pH1h, pH1l, (long long)BATCH*D_H,
                                              muW1, vW1, mub1, vb1,
                                              pH2h, pH2l, D_H, D_H, 1, 1,
                                              kk[2][0], kk[2][1], kk[3][0], kk[3][1]);
    fused_layer<<<dim3(D_H/64, NSAMP), 256>>>(pH2h, pH2l, (long long)BATCH*D_H,
                                              muW2, vW2, mub2, vb2,
                                              pH3, nullptr, D_H, D_H, 1, 0,
                                              kk[4][0], kk[4][1], kk[5][0], kk[5][1]);
    layer3_fused<<<dim3(NSAMP, 2), 256>>>(pH3, muW3, vW3, mub3, vb3, out,
                                          kk[6][0], kk[6][1], kk[7][0], kk[7][1]);
}

// round 7
// speedup vs baseline: 1.0143x; 1.0143x over previous
#include <cuda_runtime.h>
#include <stdint.h>

#define NSAMP 150
#define D_IN  784
#define D_H   512
#define D_OUT 10
#define BATCH 64

// ---------------- device scratch: activations (plain fp32) ----------------
__device__ __align__(16) float g_H1[NSAMP * BATCH * D_H];
__device__ __align__(16) float g_H2[NSAMP * BATCH * D_H];
__device__ __align__(16) float g_H3[NSAMP * BATCH * D_H];

// ---------------- tf32 helpers ----------------
__device__ __forceinline__ void tf32_split(float a, float& hi, float& lo) {
    uint32_t h, l;
    asm("cvt.rna.tf32.f32 %0, %1;" : "=r"(h) : "f"(a));
    float lf = a - __uint_as_float(h);
    asm("cvt.rna.tf32.f32 %0, %1;" : "=r"(l) : "f"(lf));
    hi = __uint_as_float(h); lo = __uint_as_float(l);
}
__device__ __forceinline__ void mma_tf32(float* c,
                                         float a0, float a1, float a2, float a3,
                                         float b0, float b1) {
    asm("mma.sync.aligned.m16n8k8.row.col.f32.tf32.tf32.f32 "
        "{%0,%1,%2,%3}, {%4,%5,%6,%7}, {%8,%9}, {%0,%1,%2,%3};"
        : "+f"(c[0]), "+f"(c[1]), "+f"(c[2]), "+f"(c[3])
        : "r"(__float_as_uint(a0)), "r"(__float_as_uint(a1)),
          "r"(__float_as_uint(a2)), "r"(__float_as_uint(a3)),
          "r"(__float_as_uint(b0)), "r"(__float_as_uint(b1)));
}

// ---------------- threefry2x32 (20 rounds), bit-exact vs jax._src.prng ----------------
__device__ __forceinline__ void tf_round(uint32_t& x0, uint32_t& x1, int r) {
    x0 += x1;
    x1 = __funnelshift_l(x1, x1, r);
    x1 ^= x0;
}
__device__ __forceinline__ uint2 threefry2x32_dev(uint32_t k0, uint32_t k1,
                                                  uint32_t x0, uint32_t x1) {
    uint32_t k2 = k0 ^ k1 ^ 0x1BD11BDAu;
    x0 += k0; x1 += k1;
    tf_round(x0,x1,13); tf_round(x0,x1,15); tf_round(x0,x1,26); tf_round(x0,x1,6);
    x0 += k1; x1 += k2 + 1u;
    tf_round(x0,x1,17); tf_round(x0,x1,29); tf_round(x0,x1,16); tf_round(x0,x1,24);
    x0 += k2; x1 += k0 + 2u;
    tf_round(x0,x1,13); tf_round(x0,x1,15); tf_round(x0,x1,26); tf_round(x0,x1,6);
    x0 += k0; x1 += k1 + 3u;
    tf_round(x0,x1,17); tf_round(x0,x1,29); tf_round(x0,x1,16); tf_round(x0,x1,24);
    x0 += k1; x1 += k2 + 4u;
    tf_round(x0,x1,13); tf_round(x0,x1,15); tf_round(x0,x1,26); tf_round(x0,x1,6);
    x0 += k2; x1 += k0 + 5u;
    return make_uint2(x0, x1);
}

// ---------------- bits -> N(0,1): fast-math clone of XLA pipeline ----------------
__device__ __forceinline__ float jax_normal_fast(uint32_t bits) {
    const float LO = -0.99999994039535522461f;
    float f = __uint_as_float((bits >> 9) | 0x3f800000u) - 1.0f;
    float x = fmaxf(__fmaf_rn(f, 2.0f, LO), LO);
    float y = x * x;
    float t = 1.0f - y;
    float w = (t == 1.0f) ? y : -__logf(t);
    float p;
    if (w < 5.0f) {
        float ww = w - 2.5f;
        p =                2.81022636e-08f;
        p = __fmaf_rn(p, ww, 3.43273939e-07f);
        p = __fmaf_rn(p, ww, -3.5233877e-06f);
        p = __fmaf_rn(p, ww, -4.39150654e-06f);
        p = __fmaf_rn(p, ww, 0.00021858087f);
        p = __fmaf_rn(p, ww, -0.00125372503f);
        p = __fmaf_rn(p, ww, -0.00417768164f);
        p = __fmaf_rn(p, ww, 0.246640727f);
        p = __fmaf_rn(p, ww, 1.50140941f);
    } else {
        float ww = __fsqrt_rn(w) - 3.0f;
        p =                -0.000200214257f;
        p = __fmaf_rn(p, ww, 0.000100950558f);
        p = __fmaf_rn(p, ww, 0.00134934322f);
        p = __fmaf_rn(p, ww, -0.00367342844f);
        p = __fmaf_rn(p, ww, 0.00573950773f);
        p = __fmaf_rn(p, ww, -0.0076224613f);
        p = __fmaf_rn(p, ww, 0.00943887047f);
        p = __fmaf_rn(p, ww, 1.00167406f);
        p = __fmaf_rn(p, ww, 2.83297682f);
    }
    return 1.4142135623730951f * (p * x);
}

// B smem: rows 0..63 (n), 24 float2 per row (192B), k permuted: col(k) = 8g + 2q + h,
//   g = k>>3, q = k&3, h = (k>>2)&1. Consumer LDS.128 at byte row*192 + 64*ks + 16*ka
//   fetches {b(k=8ks+ka).hi/lo, b(k=8ks+ka+4).hi/lo}. Conflict-free both directions.
#define B_ROW_F2 24
// A smem: fp32 [64 rows][20 words] (16 used + 4 pad) -> all-distinct banks for frag LDS.32.
#define A_ROW_F  20

// ---------------- fused layer: gen (pre-split W) + tf32 MMA, 1 barrier/chunk --------------
__global__ __launch_bounds__(256, 2) void fused_layer(
    const float* __restrict__ A, long long strideA,
    const float* __restrict__ muW, const float* __restrict__ vW,
    const float* __restrict__ mub, const float* __restrict__ vb,
    float* __restrict__ C, int K, int N, int relu,
    uint32_t wk0, uint32_t wk1, uint32_t bk0, uint32_t bk1)
{
    const int s    = blockIdx.y;
    const int nblk = blockIdx.x;
    const int t    = threadIdx.x;      // 256

    __shared__ float  As[2][64][A_ROW_F];        // 10.2 KB
    __shared__ float2 Bs[2][64][B_ROW_F2];       // 24.6 KB
    __shared__ float  bias_s[64];

    const int lr   = t >> 2;           // 0..63 row (producer: A-row m / W-row n)
    const int lq   = t & 3;            // producer W: k base (k = lq + 4j)
    const int lk4  = (t & 3) << 2;     // producer A: k offset (contiguous 4)
    const int lane = t & 31;
    const int wrp  = t >> 5;           // 0..7
    const int m0   = (wrp & 3) * 16;
    const int n0b  = (wrp >> 2) * 32;
    const int ka   = lane & 3;
    const int ra   = lane >> 2;

    const float* Ab     = A + (long long)s * strideA;
    const int    n_glob = nblk * 64 + lr;
    const float* muRow  = muW + (long long)n_glob * K;
    const float* vRow   = vW  + (long long)n_glob * K;
    const uint32_t eBase = ((uint32_t)s * (uint32_t)N + (uint32_t)n_glob) * (uint32_t)K;

    if (t < 64) {
        int nb = nblk * 64 + t;
        uint2 r = threefry2x32_dev(bk0, bk1, 0u, (uint32_t)(s * N + nb));
        bias_s[t] = __fmaf_rn(__expf(vb[nb]), jax_normal_fast(r.x ^ r.y), mub[nb]);
    }

    // ---- producer gen for one chunk: W at k = lq, lq+4, lq+8, lq+12 -> 2 pre-split float4
    float4 av;                 // A[m=lr][k0+lk4 .. +3]
    float4 wg0, wg1;           // {hi,lo,hi,lo} for (lq, lq+4) and (lq+8, lq+12)
    {
        av = *(const float4*)(Ab + (long long)lr * K + lk4);
        float m_[4], v_[4];
#pragma unroll
        for (int j = 0; j < 4; j++) { m_[j] = muRow[lq + 4*j]; v_[j] = vRow[lq + 4*j]; }
        uint32_t e0 = eBase + lq;
        uint2 r0 = threefry2x32_dev(wk0, wk1, 0u, e0 + 0);
        uint2 r1 = threefry2x32_dev(wk0, wk1, 0u, e0 + 4);
        uint2 r2 = threefry2x32_dev(wk0, wk1, 0u, e0 + 8);
        uint2 r3 = threefry2x32_dev(wk0, wk1, 0u, e0 + 12);
        float w0 = __fmaf_rn(__expf(v_[0]), jax_normal_fast(r0.x ^ r0.y), m_[0]);
        float w1 = __fmaf_rn(__expf(v_[1]), jax_normal_fast(r1.x ^ r1.y), m_[1]);
        float w2 = __fmaf_rn(__expf(v_[2]), jax_normal_fast(r2.x ^ r2.y), m_[2]);
        float w3 = __fmaf_rn(__expf(v_[3]), jax_normal_fast(r3.x ^ r3.y), m_[3]);
        tf32_split(w0, wg0.x, wg0.y); tf32_split(w1, wg0.z, wg0.w);
        tf32_split(w2, wg1.x, wg1.y); tf32_split(w3, wg1.z, wg1.w);
    }

    float acc[4][4];
#pragma unroll
    for (int i = 0; i < 4; i++)
#pragma unroll
        for (int j = 0; j < 4; j++) acc[i][j] = 0.0f;

    const int nch = K >> 4;

    for (int c = 0; c < nch; c++) {
        const int buf = c & 1;
        // store chunk c
        *(float4*)&As[buf][lr][lk4] = av;
        {
            float* brow = (float*)&Bs[buf][lr][0];
            *(float4*)(brow + 4 * lq)      = wg0;   // bytes 16*lq       (g=0)
            *(float4*)(brow + 16 + 4 * lq) = wg1;   // bytes 64 + 16*lq  (g=1)
        }
        __syncthreads();

        if (c + 1 < nch) {
            const int k0n = (c + 1) << 4;
            av = *(const float4*)(Ab + (long long)lr * K + k0n + lk4);
            float m_[4], v_[4];
#pragma unroll
            for (int j = 0; j < 4; j++) {
                m_[j] = muRow[k0n + lq + 4*j];
                v_[j] = vRow [k0n + lq + 4*j];
            }
            uint32_t e0 = eBase + (uint32_t)(k0n + lq);
            uint2 r0 = threefry2x32_dev(wk0, wk1, 0u, e0 + 0);
            uint2 r1 = threefry2x32_dev(wk0, wk1, 0u, e0 + 4);
            uint2 r2 = threefry2x32_dev(wk0, wk1, 0u, e0 + 8);
            uint2 r3 = threefry2x32_dev(wk0, wk1, 0u, e0 + 12);
            float w0 = __fmaf_rn(__expf(v_[0]), jax_normal_fast(r0.x ^ r0.y), m_[0]);
            float w1 = __fmaf_rn(__expf(v_[1]), jax_normal_fast(r1.x ^ r1.y), m_[1]);
            float w2 = __fmaf_rn(__expf(v_[2]), jax_normal_fast(r2.x ^ r2.y), m_[2]);
            float w3 = __fmaf_rn(__expf(v_[3]), jax_normal_fast(r3.x ^ r3.y), m_[3]);
            tf32_split(w0, wg0.x, wg0.y); tf32_split(w1, wg0.z, wg0.w);
            tf32_split(w2, wg1.x, wg1.y); tf32_split(w3, wg1.z, wg1.w);
        }

        // consumer: A fp32 (split here), B pre-split via single LDS.128 per fragment
#pragma unroll
        for (int ks = 0; ks < 2; ks++) {
            const int kb = ks * 8;
            float a0f = As[buf][m0 + ra    ][kb + ka    ];
            float a1f = As[buf][m0 + ra + 8][kb + ka    ];
            float a2f = As[buf][m0 + ra    ][kb + ka + 4];
            float a3f = As[buf][m0 + ra + 8][kb + ka + 4];
            float a0h, a0l, a1h, a1l, a2h, a2l, a3h, a3l;
            tf32_split(a0f, a0h, a0l); tf32_split(a1f, a1h, a1l);
            tf32_split(a2f, a2h, a2l); tf32_split(a3f, a3h, a3l);
#pragma unroll
            for (int tj = 0; tj < 4; tj++) {
                const float* brow = (const float*)&Bs[buf][n0b + tj * 8 + ra][0];
                float4 bv = *(const float4*)(brow + 16 * ks + 4 * ka);
                // bv = {b0h, b0l, b1h, b1l}
                mma_tf32(acc[tj], a0l, a1l, a2l, a3l, bv.x, bv.z);  // alo*bhi
                mma_tf32(acc[tj], a0h, a1h, a2h, a3h, bv.y, bv.w);  // ahi*blo
                mma_tf32(acc[tj], a0h, a1h, a2h, a3h, bv.x, bv.z);  // ahi*bhi
            }
        }
    }

    // ---- epilogue: +bias, relu, store fp32 ----
    const int row0 = m0 + ra;
    const int row1 = m0 + ra + 8;
#pragma unroll
    for (int tj = 0; tj < 4; tj++) {
        int n = n0b + tj * 8 + 2 * ka;
        float bb0 = bias_s[n], bb1 = bias_s[n + 1];
        float v00 = acc[tj][0] + bb0, v01 = acc[tj][1] + bb1;
        float v10 = acc[tj][2] + bb0, v11 = acc[tj][3] + bb1;
        if (relu) {
            v00 = fmaxf(v00, 0.f); v01 = fmaxf(v01, 0.f);
            v10 = fmaxf(v10, 0.f); v11 = fmaxf(v11, 0.f);
        }
        long long o0 = ((long long)s * 64 + row0) * N + nblk * 64 + n;
        long long o1 = ((long long)s * 64 + row1) * N + nblk * 64 + n;
        *(float2*)(C + o0) = make_float2(v00, v01);
        *(float2*)(C + o1) = make_float2(v10, v11);
    }
}

// ---------------- final layer: 2 blocks/sample, gen partitioned by output-half ----------
__global__ __launch_bounds__(256) void layer3_fused(
    const float* __restrict__ H,
    const float* __restrict__ muW, const float* __restrict__ vW,
    const float* __restrict__ mub, const float* __restrict__ vb,
    float* __restrict__ out,
    uint32_t wk0, uint32_t wk1, uint32_t bk0, uint32_t bk1)
{
    const int s = blockIdx.x;
    const int h = blockIdx.y;
    const int t = threadIdx.x;
    __shared__ float Ws[5 * D_H];
    __shared__ float bsm[5];

#pragma unroll
    for (int i = 0; i < (5 * D_H) / 256; i++) {
        int j = t + 256 * i;
        uint32_t e = (uint32_t)(s * (D_OUT * D_H) + h * (5 * D_H) + j);
        uint2 r = threefry2x32_dev(wk0, wk1, 0u, e);
        int jg = h * (5 * D_H) + j;
        Ws[j] = __fmaf_rn(__expf(vW[jg]), jax_normal_fast(r.x ^ r.y), muW[jg]);
    }
    if (t < 5) {
        int og = h * 5 + t;
        uint2 r = threefry2x32_dev(bk0, bk1, 0u, (uint32_t)(s * D_OUT + og));
        bsm[t] = __fmaf_rn(__expf(vb[og]), jax_normal_fast(r.x ^ r.y), mub[og]);
    }
    __syncthreads();

    const int w = t >> 5, l = t & 31;
#pragma unroll
    for (int ri = 0; ri < 8; ri++) {
        int b = w * 8 + ri;
        const float* Hb = H + ((long long)s * BATCH + b) * D_H;
        float hh[16];
#pragma unroll
        for (int i = 0; i < 16; i++) hh[i] = Hb[l + 32 * i];
#pragma unroll
        for (int o = 0; o < 5; o++) {
            float acc = 0.0f;
#pragma unroll
            for (int i = 0; i < 16; i++)
                acc = __fmaf_rn(hh[i], Ws[o * D_H + l + 32 * i], acc);
            acc += __shfl_xor_sync(0xffffffffu, acc, 16);
            acc += __shfl_xor_sync(0xffffffffu, acc, 8);
            acc += __shfl_xor_sync(0xffffffffu, acc, 4);
            acc += __shfl_xor_sync(0xffffffffu, acc, 2);
            acc += __shfl_xor_sync(0xffffffffu, acc, 1);
            if (l == 0)
                out[((long long)s * BATCH + b) * D_OUT + h * 5 + o] = acc + bsm[o];
        }
    }
}

// ---------------- host-side threefry (subkey derivation) ----------------
static inline uint32_t h_rotl(uint32_t x, int r) { return (x << r) | (x >> (32 - r)); }
static void tf_host(uint32_t k0, uint32_t k1, uint32_t x0, uint32_t x1,
                    uint32_t* o0, uint32_t* o1) {
    uint32_t k2 = k0 ^ k1 ^ 0x1BD11BDAu;
    x0 += k0; x1 += k1;
    static const int R[2][4] = {{13,15,26,6},{17,29,16,24}};
    const uint32_t ks[3] = {k0, k1, k2};
    for (int i = 0; i < 5; i++) {
        for (int r = 0; r < 4; r++) {
            x0 += x1; x1 = h_rotl(x1, R[i & 1][r]); x1 ^= x0;
        }
        x0 += ks[(i + 1) % 3];
        x1 += ks[(i + 2) % 3] + (uint32_t)(i + 1);
    }
    *o0 = x0; *o1 = x1;
}

extern "C" void kernel_launch(void* const* d_in, const int* in_sizes, int n_in,
                              void* d_out, int out_size) {
    const float* x    = (const float*)d_in[0];
    const float* muW0 = (const float*)d_in[1];
    const float* mub0 = (const float*)d_in[2];
    const float* muW1 = (const float*)d_in[3];
    const float* mub1 = (const float*)d_in[4];
    const float* muW2 = (const float*)d_in[5];
    const float* mub2 = (const float*)d_in[6];
    const float* muW3 = (const float*)d_in[7];
    const float* mub3 = (const float*)d_in[8];
    const float* vW0  = (const float*)d_in[9];
    const float* vb0  = (const float*)d_in[10];
    const float* vW1  = (const float*)d_in[11];
    const float* vb1  = (const float*)d_in[12];
    const float* vW2  = (const float*)d_in[13];
    const float* vb2  = (const float*)d_in[14];
    const float* vW3  = (const float*)d_in[15];
    const float* vb3  = (const float*)d_in[16];
    float* out = (float*)d_out;

    uint32_t kk[8][2];
    for (int i = 0; i < 8; i++) tf_host(0u, 1u, 0u, (uint32_t)i, &kk[i][0], &kk[i][1]);

    float *pH1, *pH2, *pH3;
    cudaGetSymbolAddress((void**)&pH1, g_H1);
    cudaGetSymbolAddress((void**)&pH2, g_H2);
    cudaGetSymbolAddress((void**)&pH3, g_H3);

    fused_layer<<<dim3(D_H/64, NSAMP), 256>>>(x,   0,
                                              muW0, vW0, mub0, vb0,
                                              pH1, D_IN, D_H, 1,
                                              kk[0][0], kk[0][1], kk[1][0], kk[1][1]);
    fused_layer<<<dim3(D_H/64, NSAMP), 256>>>(pH1, (long long)BATCH*D_H,
                                              muW1, vW1, mub1, vb1,
                                              pH2, D_H, D_H, 1,
                                              kk[2][0], kk[2][1], kk[3][0], kk[3][1]);
    fused_layer<<<dim3(D_H/64, NSAMP), 256>>>(pH2, (long long)BATCH*D_H,
                                              muW2, vW2, mub2, vb2,
                                              pH3, D_H, D_H, 1,
                                              kk[4][0], kk[4][1], kk[5][0], kk[5][1]);
    layer3_fused<<<dim3(NSAMP, 2), 256>>>(pH3, muW3, vW3, mub3, vb3, out,
                                          kk[6][0], kk[6][1], kk[7][0], kk[7][1]);
}

// round 8
// speedup vs baseline: 1.0425x; 1.0278x over previous
#include <cuda_runtime.h>
#include <stdint.h>

#define NSAMP 150
#define D_IN  784
#define D_H   512
#define D_OUT 10
#define BATCH 64

// ---------------- device scratch: activations only ----------------
__device__ __align__(16) float g_H1[NSAMP * BATCH * D_H];
__device__ __align__(16) float g_H2[NSAMP * BATCH * D_H];
__device__ __align__(16) float g_H3[NSAMP * BATCH * D_H];

// ---------------- tf32 helpers (3xTF32 error-compensated GEMM) ----------------
__device__ __forceinline__ void tf32_split(float a, uint32_t& hi, uint32_t& lo) {
    asm("cvt.rna.tf32.f32 %0, %1;" : "=r"(hi) : "f"(a));
    float l = a - __uint_as_float(hi);            // exact (hi has <=11-bit mantissa)
    asm("cvt.rna.tf32.f32 %0, %1;" : "=r"(lo) : "f"(l));
}
__device__ __forceinline__ void mma_tf32(float* c,
                                         uint32_t a0, uint32_t a1, uint32_t a2, uint32_t a3,
                                         uint32_t b0, uint32_t b1) {
    asm("mma.sync.aligned.m16n8k8.row.col.f32.tf32.tf32.f32 "
        "{%0,%1,%2,%3}, {%4,%5,%6,%7}, {%8,%9}, {%0,%1,%2,%3};"
        : "+f"(c[0]), "+f"(c[1]), "+f"(c[2]), "+f"(c[3])
        : "r"(a0), "r"(a1), "r"(a2), "r"(a3), "r"(b0), "r"(b1));
}

// ---------------- threefry2x32 (20 rounds), bit-exact vs jax._src.prng ----------------
__device__ __forceinline__ void tf_round(uint32_t& x0, uint32_t& x1, int r) {
    x0 += x1;
    x1 = __funnelshift_l(x1, x1, r);
    x1 ^= x0;
}
__device__ __forceinline__ uint2 threefry2x32_dev(uint32_t k0, uint32_t k1,
                                                  uint32_t x0, uint32_t x1) {
    uint32_t k2 = k0 ^ k1 ^ 0x1BD11BDAu;
    x0 += k0; x1 += k1;
    tf_round(x0,x1,13); tf_round(x0,x1,15); tf_round(x0,x1,26); tf_round(x0,x1,6);
    x0 += k1; x1 += k2 + 1u;
    tf_round(x0,x1,17); tf_round(x0,x1,29); tf_round(x0,x1,16); tf_round(x0,x1,24);
    x0 += k2; x1 += k0 + 2u;
    tf_round(x0,x1,13); tf_round(x0,x1,15); tf_round(x0,x1,26); tf_round(x0,x1,6);
    x0 += k0; x1 += k1 + 3u;
    tf_round(x0,x1,17); tf_round(x0,x1,29); tf_round(x0,x1,16); tf_round(x0,x1,24);
    x0 += k1; x1 += k2 + 4u;
    tf_round(x0,x1,13); tf_round(x0,x1,15); tf_round(x0,x1,26); tf_round(x0,x1,6);
    x0 += k2; x1 += k0 + 5u;
    return make_uint2(x0, x1);
}

// ---------------- bits -> N(0,1): fast-math clone of XLA pipeline ----------------
__device__ __forceinline__ float jax_normal_fast(uint32_t bits) {
    const float LO = -0.99999994039535522461f;
    float f = __uint_as_float((bits >> 9) | 0x3f800000u) - 1.0f;
    float x = fmaxf(__fmaf_rn(f, 2.0f, LO), LO);
    float y = x * x;
    float t = 1.0f - y;
    float w = (t == 1.0f) ? y : -__logf(t);
    float p;
    if (w < 5.0f) {
        float ww = w - 2.5f;
        p =                2.81022636e-08f;
        p = __fmaf_rn(p, ww, 3.43273939e-07f);
        p = __fmaf_rn(p, ww, -3.5233877e-06f);
        p = __fmaf_rn(p, ww, -4.39150654e-06f);
        p = __fmaf_rn(p, ww, 0.00021858087f);
        p = __fmaf_rn(p, ww, -0.00125372503f);
        p = __fmaf_rn(p, ww, -0.00417768164f);
        p = __fmaf_rn(p, ww, 0.246640727f);
        p = __fmaf_rn(p, ww, 1.50140941f);
    } else {
        float ww = __fsqrt_rn(w) - 3.0f;
        p =                -0.000200214257f;
        p = __fmaf_rn(p, ww, 0.000100950558f);
        p = __fmaf_rn(p, ww, 0.00134934322f);
        p = __fmaf_rn(p, ww, -0.00367342844f);
        p = __fmaf_rn(p, ww, 0.00573950773f);
        p = __fmaf_rn(p, ww, -0.0076224613f);
        p = __fmaf_rn(p, ww, 0.00943887047f);
        p = __fmaf_rn(p, ww, 1.00167406f);
        p = __fmaf_rn(p, ww, 2.83297682f);
    }
    return 1.4142135623730951f * (p * x);
}

// ---------------- fused layer: 64x64 tile, double-buffered gen pipeline + tf32 MMA --------
// C[s, 0:64, nblk*64..+64] = relu(A[s] @ W[s]^T + b[s])
__global__ __launch_bounds__(256, 3) void fused_layer(
    const float* __restrict__ A, long long strideA,
    const float* __restrict__ muW, const float* __restrict__ vW,
    const float* __restrict__ mub, const float* __restrict__ vb,
    float* __restrict__ C, int K, int N, int relu,
    uint32_t wk0, uint32_t wk1, uint32_t bk0, uint32_t bk1)
{
    const int s    = blockIdx.y;
    const int nblk = blockIdx.x;
    const int t    = threadIdx.x;      // 256

    __shared__ float As[2][16][68];    // [buf][k][m]
    __shared__ float Bs[2][16][68];    // [buf][k][n]
    __shared__ float bias_s[64];

    const int lr   = t >> 2;           // 0..63 row (A-row / W-row) for producer
    const int lk4  = (t & 3) << 2;     // k offset 0,4,8,12
    const int lane = t & 31;
    const int wrp  = t >> 5;           // 0..7
    const int m0   = (wrp & 3) * 16;   // m-group of this warp
    const int n0b  = (wrp >> 2) * 32;  // n-half of this warp (4 n8-tiles)
    const int ka   = lane & 3;         // k within k8 (fragment)
    const int ra   = lane >> 2;        // row/col within fragment

    const float* Ab     = A + (long long)s * strideA;
    const int    n_glob = nblk * 64 + lr;
    const float* muRow  = muW + (long long)n_glob * K;
    const float* vRow   = vW  + (long long)n_glob * K;
    const uint32_t eBase = ((uint32_t)s * (uint32_t)N + (uint32_t)n_glob) * (uint32_t)K;

    if (t < 64) {
        int nb = nblk * 64 + t;
        uint2 r = threefry2x32_dev(bk0, bk1, 0u, (uint32_t)(s * N + nb));
        bias_s[t] = __fmaf_rn(__expf(vb[nb]), jax_normal_fast(r.x ^ r.y), mub[nb]);
    }

    // ---- prologue: load + gen chunk 0 into registers ----
    float4 av = *(const float4*)(Ab + (long long)lr * K + lk4);
    float4 mv = *(const float4*)(muRow + lk4);
    float4 vv = *(const float4*)(vRow  + lk4);
    float w0, w1, w2, w3;
    {
        uint32_t e0 = eBase + lk4;
        uint2 r0 = threefry2x32_dev(wk0, wk1, 0u, e0 + 0);
        uint2 r1 = threefry2x32_dev(wk0, wk1, 0u, e0 + 1);
        uint2 r2 = threefry2x32_dev(wk0, wk1, 0u, e0 + 2);
        uint2 r3 = threefry2x32_dev(wk0, wk1, 0u, e0 + 3);
        w0 = __fmaf_rn(__expf(vv.x), jax_normal_fast(r0.x ^ r0.y), mv.x);
        w1 = __fmaf_rn(__expf(vv.y), jax_normal_fast(r1.x ^ r1.y), mv.y);
        w2 = __fmaf_rn(__expf(vv.z), jax_normal_fast(r2.x ^ r2.y), mv.z);
        w3 = __fmaf_rn(__expf(vv.w), jax_normal_fast(r3.x ^ r3.y), mv.w);
    }

    float acc[4][4];                   // [n8-tile][c-fragment]
#pragma unroll
    for (int i = 0; i < 4; i++)
#pragma unroll
        for (int j = 0; j < 4; j++) acc[i][j] = 0.0f;

    const int nch = K >> 4;

    // ---- main loop: store(c) | sync | gen(c+1) | MMA(c) -- single barrier per chunk ----
    for (int c = 0; c < nch; c++) {
        const int buf = c & 1;
        As[buf][lk4+0][lr] = av.x; As[buf][lk4+1][lr] = av.y;
        As[buf][lk4+2][lr] = av.z; As[buf][lk4+3][lr] = av.w;
        Bs[buf][lk4+0][lr] = w0;   Bs[buf][lk4+1][lr] = w1;
        Bs[buf][lk4+2][lr] = w2;   Bs[buf][lk4+3][lr] = w3;
        __syncthreads();

        if (c + 1 < nch) {
            // load + gen next chunk (ALU/MUFU work; interleaves with MMA below)
            const int k0n = (c + 1) << 4;
            av = *(const float4*)(Ab + (long long)lr * K + k0n + lk4);
            mv = *(const float4*)(muRow + k0n + lk4);
            vv = *(const float4*)(vRow  + k0n + lk4);
            uint32_t e0 = eBase + (uint32_t)(k0n + lk4);
            uint2 r0 = threefry2x32_dev(wk0, wk1, 0u, e0 + 0);
            uint2 r1 = threefry2x32_dev(wk0, wk1, 0u, e0 + 1);
            uint2 r2 = threefry2x32_dev(wk0, wk1, 0u, e0 + 2);
            uint2 r3 = threefry2x32_dev(wk0, wk1, 0u, e0 + 3);
            w0 = __fmaf_rn(__expf(vv.x), jax_normal_fast(r0.x ^ r0.y), mv.x);
            w1 = __fmaf_rn(__expf(vv.y), jax_normal_fast(r1.x ^ r1.y), mv.y);
            w2 = __fmaf_rn(__expf(vv.z), jax_normal_fast(r2.x ^ r2.y), mv.z);
            w3 = __fmaf_rn(__expf(vv.w), jax_normal_fast(r3.x ^ r3.y), mv.w);
        }

        // MMA over chunk c: 2 k8-steps x 4 n8-tiles, 3xTF32
#pragma unroll
        for (int ks = 0; ks < 2; ks++) {
            const int kb = ks * 8;
            float a0f = As[buf][kb + ka    ][m0 + ra    ];
            float a1f = As[buf][kb + ka    ][m0 + ra + 8];
            float a2f = As[buf][kb + ka + 4][m0 + ra    ];
            float a3f = As[buf][kb + ka + 4][m0 + ra + 8];
            uint32_t ah0, al0, ah1, al1, ah2, al2, ah3, al3;
            tf32_split(a0f, ah0, al0); tf32_split(a1f, ah1, al1);
            tf32_split(a2f, ah2, al2); tf32_split(a3f, ah3, al3);
#pragma unroll
            for (int tj = 0; tj < 4; tj++) {
                float b0f = Bs[buf][kb + ka    ][n0b + tj * 8 + ra];
                float b1f = Bs[buf][kb + ka + 4][n0b + tj * 8 + ra];
                uint32_t bh0, bl0, bh1, bl1;
                tf32_split(b0f, bh0, bl0);
                tf32_split(b1f, bh1, bl1);
                mma_tf32(acc[tj], al0, al1, al2, al3, bh0, bh1);  // alo*bhi
                mma_tf32(acc[tj], ah0, ah1, ah2, ah3, bl0, bl1);  // ahi*blo
                mma_tf32(acc[tj], ah0, ah1, ah2, ah3, bh0, bh1);  // ahi*bhi
            }
        }
    }

    // ---- epilogue: fragment layout -> gmem, +bias, relu ----
    const int row0 = m0 + ra;
    const int row1 = m0 + ra + 8;
#pragma unroll
    for (int tj = 0; tj < 4; tj++) {
        int n = n0b + tj * 8 + 2 * ka;              // 2 adjacent cols per lane
        float bb0 = bias_s[n], bb1 = bias_s[n + 1];
        float v00 = acc[tj][0] + bb0, v01 = acc[tj][1] + bb1;
        float v10 = acc[tj][2] + bb0, v11 = acc[tj][3] + bb1;
        if (relu) {
            v00 = fmaxf(v00, 0.f); v01 = fmaxf(v01, 0.f);
            v10 = fmaxf(v10, 0.f); v11 = fmaxf(v11, 0.f);
        }
        float* p0 = C + ((long long)s * 64 + row0) * N + nblk * 64 + n;
        float* p1 = C + ((long long)s * 64 + row1) * N + nblk * 64 + n;
        *(float2*)p0 = make_float2(v00, v01);
        *(float2*)p1 = make_float2(v10, v11);
    }
}

// ---------------- final layer: 2 blocks per sample, gen partitioned by output-half --------
__global__ __launch_bounds__(256) void layer3_fused(
    const float* __restrict__ H,
    const float* __restrict__ muW, const float* __restrict__ vW,
    const float* __restrict__ mub, const float* __restrict__ vb,
    float* __restrict__ out,
    uint32_t wk0, uint32_t wk1, uint32_t bk0, uint32_t bk1)
{
    const int s = blockIdx.x;
    const int h = blockIdx.y;          // output half: o in [5h, 5h+5)
    const int t = threadIdx.x;
    __shared__ float Ws[5 * D_H];
    __shared__ float bsm[5];

#pragma unroll
    for (int i = 0; i < (5 * D_H) / 256; i++) {     // 10 iters
        int j = t + 256 * i;
        uint32_t e = (uint32_t)(s * (D_OUT * D_H) + h * (5 * D_H) + j);
        uint2 r = threefry2x32_dev(wk0, wk1, 0u, e);
        int jg = h * (5 * D_H) + j;
        Ws[j] = __fmaf_rn(__expf(vW[jg]), jax_normal_fast(r.x ^ r.y), muW[jg]);
    }
    if (t < 5) {
        int og = h * 5 + t;
        uint2 r = threefry2x32_dev(bk0, bk1, 0u, (uint32_t)(s * D_OUT + og));
        bsm[t] = __fmaf_rn(__expf(vb[og]), jax_normal_fast(r.x ^ r.y), mub[og]);
    }
    __syncthreads();

    const int w = t >> 5, l = t & 31;
#pragma unroll
    for (int ri = 0; ri < 8; ri++) {
        int b = w * 8 + ri;
        const float* Hb = H + ((long long)s * BATCH + b) * D_H;
        float hh[16];
#pragma unroll
        for (int i = 0; i < 16; i++) hh[i] = Hb[l + 32 * i];
#pragma unroll
        for (int o = 0; o < 5; o++) {
            float acc = 0.0f;
#pragma unroll
            for (int i = 0; i < 16; i++)
                acc = __fmaf_rn(hh[i], Ws[o * D_H + l + 32 * i], acc);
            acc += __shfl_xor_sync(0xffffffffu, acc, 16);
            acc += __shfl_xor_sync(0xffffffffu, acc, 8);
            acc += __shfl_xor_sync(0xffffffffu, acc, 4);
            acc += __shfl_xor_sync(0xffffffffu, acc, 2);
            acc += __shfl_xor_sync(0xffffffffu, acc, 1);
            if (l == 0)
                out[((long long)s * BATCH + b) * D_OUT + h * 5 + o] = acc + bsm[o];
        }
    }
}

// ---------------- host-side threefry (subkey derivation) ----------------
static inline uint32_t h_rotl(uint32_t x, int r) { return (x << r) | (x >> (32 - r)); }
static void tf_host(uint32_t k0, uint32_t k1, uint32_t x0, uint32_t x1,
                    uint32_t* o0, uint32_t* o1) {
    uint32_t k2 = k0 ^ k1 ^ 0x1BD11BDAu;
    x0 += k0; x1 += k1;
    static const int R[2][4] = {{13,15,26,6},{17,29,16,24}};
    const uint32_t ks[3] = {k0, k1, k2};
    for (int i = 0; i < 5; i++) {
        for (int r = 0; r < 4; r++) {
            x0 += x1; x1 = h_rotl(x1, R[i & 1][r]); x1 ^= x0;
        }
        x0 += ks[(i + 1) % 3];
        x1 += ks[(i + 2) % 3] + (uint32_t)(i + 1);
    }
    *o0 = x0; *o1 = x1;
}

extern "C" void kernel_launch(void* const* d_in, const int* in_sizes, int n_in,
                              void* d_out, int out_size) {
    const float* x    = (const float*)d_in[0];
    const float* muW0 = (const float*)d_in[1];
    const float* mub0 = (const float*)d_in[2];
    const float* muW1 = (const float*)d_in[3];
    const float* mub1 = (const float*)d_in[4];
    const float* muW2 = (const float*)d_in[5];
    const float* mub2 = (const float*)d_in[6];
    const float* muW3 = (const float*)d_in[7];
    const float* mub3 = (const float*)d_in[8];
    const float* vW0  = (const float*)d_in[9];
    const float* vb0  = (const float*)d_in[10];
    const float* vW1  = (const float*)d_in[11];
    const float* vb1  = (const float*)d_in[12];
    const float* vW2  = (const float*)d_in[13];
    const float* vb2  = (const float*)d_in[14];
    const float* vW3  = (const float*)d_in[15];
    const float* vb3  = (const float*)d_in[16];
    float* out = (float*)d_out;

    uint32_t kk[8][2];
    for (int i = 0; i < 8; i++) tf_host(0u, 1u, 0u, (uint32_t)i, &kk[i][0], &kk[i][1]);

    float *pH1, *pH2, *pH3;
    cudaGetSymbolAddress((void**)&pH1, g_H1);
    cudaGetSymbolAddress((void**)&pH2, g_H2);
    cudaGetSymbolAddress((void**)&pH3, g_H3);

    fused_layer<<<dim3(D_H/64, NSAMP), 256>>>(x,   0,
                                              muW0, vW0, mub0, vb0,
                                              pH1, D_IN, D_H, 1,
                                              kk[0][0], kk[0][1], kk[1][0], kk[1][1]);
    fused_layer<<<dim3(D_H/64, NSAMP), 256>>>(pH1, (long long)BATCH*D_H,
                                              muW1, vW1, mub1, vb1,
                                              pH2, D_H, D_H, 1,
                                              kk[2][0], kk[2][1], kk[3][0], kk[3][1]);
    fused_layer<<<dim3(D_H/64, NSAMP), 256>>>(pH2, (long long)BATCH*D_H,
                                              muW2, vW2, mub2, vb2,
                                              pH3, D_H, D_H, 1,
                                              kk[4][0], kk[4][1], kk[5][0], kk[5][1]);
    layer3_fused<<<dim3(NSAMP, 2), 256>>>(pH3, muW3, vW3, mub3, vb3, out,
                                          kk[6][0], kk[6][1], kk[7][0], kk[7][1]);
}

// round 9
// speedup vs baseline: 1.2453x; 1.1946x over previous
#include <cuda_runtime.h>
#include <stdint.h>

#define NSAMP 150
#define D_IN  784
#define D_H   512
#define D_OUT 10
#define BATCH 64

// ---------------- device scratch: activations only ----------------
__device__ __align__(16) float g_H1[NSAMP * BATCH * D_H];
__device__ __align__(16) float g_H2[NSAMP * BATCH * D_H];
__device__ __align__(16) float g_H3[NSAMP * BATCH * D_H];

// ---------------- tf32 helpers ----------------
__device__ __forceinline__ float tf32_round(float a) {
    uint32_t h;
    asm("cvt.rna.tf32.f32 %0, %1;" : "=r"(h) : "f"(a));
    return __uint_as_float(h);
}
__device__ __forceinline__ void tf32_split(float a, uint32_t& hi, uint32_t& lo) {
    asm("cvt.rna.tf32.f32 %0, %1;" : "=r"(hi) : "f"(a));
    float l = a - __uint_as_float(hi);            // exact
    asm("cvt.rna.tf32.f32 %0, %1;" : "=r"(lo) : "f"(l));
}
__device__ __forceinline__ void mma_tf32(float* c,
                                         uint32_t a0, uint32_t a1, uint32_t a2, uint32_t a3,
                                         uint32_t b0, uint32_t b1) {
    asm("mma.sync.aligned.m16n8k8.row.col.f32.tf32.tf32.f32 "
        "{%0,%1,%2,%3}, {%4,%5,%6,%7}, {%8,%9}, {%0,%1,%2,%3};"
        : "+f"(c[0]), "+f"(c[1]), "+f"(c[2]), "+f"(c[3])
        : "r"(a0), "r"(a1), "r"(a2), "r"(a3), "r"(b0), "r"(b1));
}

// ---------------- threefry2x32 (20 rounds), bit-exact vs jax._src.prng ----------------
__device__ __forceinline__ void tf_round(uint32_t& x0, uint32_t& x1, int r) {
    x0 += x1;
    x1 = __funnelshift_l(x1, x1, r);
    x1 ^= x0;
}
__device__ __forceinline__ uint2 threefry2x32_dev(uint32_t k0, uint32_t k1,
                                                  uint32_t x0, uint32_t x1) {
    uint32_t k2 = k0 ^ k1 ^ 0x1BD11BDAu;
    x0 += k0; x1 += k1;
    tf_round(x0,x1,13); tf_round(x0,x1,15); tf_round(x0,x1,26); tf_round(x0,x1,6);
    x0 += k1; x1 += k2 + 1u;
    tf_round(x0,x1,17); tf_round(x0,x1,29); tf_round(x0,x1,16); tf_round(x0,x1,24);
    x0 += k2; x1 += k0 + 2u;
    tf_round(x0,x1,13); tf_round(x0,x1,15); tf_round(x0,x1,26); tf_round(x0,x1,6);
    x0 += k0; x1 += k1 + 3u;
    tf_round(x0,x1,17); tf_round(x0,x1,29); tf_round(x0,x1,16); tf_round(x0,x1,24);
    x0 += k1; x1 += k2 + 4u;
    tf_round(x0,x1,13); tf_round(x0,x1,15); tf_round(x0,x1,26); tf_round(x0,x1,6);
    x0 += k2; x1 += k0 + 5u;
    return make_uint2(x0, x1);
}

// ---------------- bits -> N(0,1): fast-math clone of XLA pipeline ----------------
__device__ __forceinline__ float jax_normal_fast(uint32_t bits) {
    const float LO = -0.99999994039535522461f;
    float f = __uint_as_float((bits >> 9) | 0x3f800000u) - 1.0f;
    float x = fmaxf(__fmaf_rn(f, 2.0f, LO), LO);
    float y = x * x;
    float t = 1.0f - y;
    float w = (t == 1.0f) ? y : -__logf(t);
    float p;
    if (w < 5.0f) {
        float ww = w - 2.5f;
        p =                2.81022636e-08f;
        p = __fmaf_rn(p, ww, 3.43273939e-07f);
        p = __fmaf_rn(p, ww, -3.5233877e-06f);
        p = __fmaf_rn(p, ww, -4.39150654e-06f);
        p = __fmaf_rn(p, ww, 0.00021858087f);
        p = __fmaf_rn(p, ww, -0.00125372503f);
        p = __fmaf_rn(p, ww, -0.00417768164f);
        p = __fmaf_rn(p, ww, 0.246640727f);
        p = __fmaf_rn(p, ww, 1.50140941f);
    } else {
        float ww = __fsqrt_rn(w) - 3.0f;
        p =                -0.000200214257f;
        p = __fmaf_rn(p, ww, 0.000100950558f);
        p = __fmaf_rn(p, ww, 0.00134934322f);
        p = __fmaf_rn(p, ww, -0.00367342844f);
        p = __fmaf_rn(p, ww, 0.00573950773f);
        p = __fmaf_rn(p, ww, -0.0076224613f);
        p = __fmaf_rn(p, ww, 0.00943887047f);
        p = __fmaf_rn(p, ww, 1.00167406f);
        p = __fmaf_rn(p, ww, 2.83297682f);
    }
    return 1.4142135623730951f * (p * x);
}

// gen 4 weights at k = kk..kk+3 (row n_glob), tf32-rounded
__device__ __forceinline__ void gen_w4(const float* __restrict__ muRow,
                                       const float* __restrict__ vRow,
                                       int kk, uint32_t eBase,
                                       uint32_t wk0, uint32_t wk1, float* w) {
    float4 mv = *(const float4*)(muRow + kk);
    float4 vv = *(const float4*)(vRow  + kk);
    uint32_t e0 = eBase + (uint32_t)kk;
    uint2 r0 = threefry2x32_dev(wk0, wk1, 0u, e0 + 0);
    uint2 r1 = threefry2x32_dev(wk0, wk1, 0u, e0 + 1);
    uint2 r2 = threefry2x32_dev(wk0, wk1, 0u, e0 + 2);
    uint2 r3 = threefry2x32_dev(wk0, wk1, 0u, e0 + 3);
    w[0] = tf32_round(__fmaf_rn(__expf(vv.x), jax_normal_fast(r0.x ^ r0.y), mv.x));
    w[1] = tf32_round(__fmaf_rn(__expf(vv.y), jax_normal_fast(r1.x ^ r1.y), mv.y));
    w[2] = tf32_round(__fmaf_rn(__expf(vv.z), jax_normal_fast(r2.x ^ r2.y), mv.z));
    w[3] = tf32_round(__fmaf_rn(__expf(vv.w), jax_normal_fast(r3.x ^ r3.y), mv.w));
}

// ---------------- fused layer: 64x64 tile, 32k stages, 1 barrier/stage, 2-term tf32 -------
// C[s, 0:64, nblk*64..+64] = relu(A[s] @ W[s]^T + b[s])
__global__ __launch_bounds__(256, 3) void fused_layer(
    const float* __restrict__ A, long long strideA,
    const float* __restrict__ muW, const float* __restrict__ vW,
    const float* __restrict__ mub, const float* __restrict__ vb,
    float* __restrict__ C, int K, int N, int relu,
    uint32_t wk0, uint32_t wk1, uint32_t bk0, uint32_t bk1)
{
    const int s    = blockIdx.y;
    const int nblk = blockIdx.x;
    const int t    = threadIdx.x;      // 256

    __shared__ float As[2][32][68];    // [buf][k][m]
    __shared__ float Bs[2][32][68];    // [buf][k][n]  (tf32-rounded weights)
    __shared__ float bias_s[64];

    const int lr   = t >> 2;           // 0..63 row (A-row / W-row) producer
    const int lk4  = (t & 3) << 2;     // k offset 0,4,8,12 within 16-k half
    const int lane = t & 31;
    const int wrp  = t >> 5;           // 0..7
    const int m0   = (wrp & 3) * 16;
    const int n0b  = (wrp >> 2) * 32;
    const int ka   = lane & 3;
    const int ra   = lane >> 2;

    const float* Ab     = A + (long long)s * strideA;
    const int    n_glob = nblk * 64 + lr;
    const float* muRow  = muW + (long long)n_glob * K;
    const float* vRow   = vW  + (long long)n_glob * K;
    const uint32_t eBase = ((uint32_t)s * (uint32_t)N + (uint32_t)n_glob) * (uint32_t)K;

    if (t < 64) {
        int nb = nblk * 64 + t;
        uint2 r = threefry2x32_dev(bk0, bk1, 0u, (uint32_t)(s * N + nb));
        bias_s[t] = __fmaf_rn(__expf(vb[nb]), jax_normal_fast(r.x ^ r.y), mub[nb]);
    }

    const int nst = (K + 31) >> 5;     // 32-k stages (last may be half for K=784)

    // ---- prologue: load + gen stage 0 ----
    float4 av0, av1;
    float  w[8];
    {
        av0 = *(const float4*)(Ab + (long long)lr * K + lk4);
        gen_w4(muRow, vRow, lk4, eBase, wk0, wk1, w);
        if (32 <= K) {
            av1 = *(const float4*)(Ab + (long long)lr * K + 16 + lk4);
            gen_w4(muRow, vRow, 16 + lk4, eBase, wk0, wk1, w + 4);
        } else {
            av1 = make_float4(0.f, 0.f, 0.f, 0.f);
            w[4] = w[5] = w[6] = w[7] = 0.f;
        }
    }

    float acc[4][4];
#pragma unroll
    for (int i = 0; i < 4; i++)
#pragma unroll
        for (int j = 0; j < 4; j++) acc[i][j] = 0.0f;

    // ---- main loop: store(c) | sync | gen(c+1) | MMA(c) ----
    for (int c = 0; c < nst; c++) {
        const int buf = c & 1;
        As[buf][lk4+0][lr] = av0.x; As[buf][lk4+1][lr] = av0.y;
        As[buf][lk4+2][lr] = av0.z; As[buf][lk4+3][lr] = av0.w;
        As[buf][16+lk4+0][lr] = av1.x; As[buf][16+lk4+1][lr] = av1.y;
        As[buf][16+lk4+2][lr] = av1.z; As[buf][16+lk4+3][lr] = av1.w;
        Bs[buf][lk4+0][lr] = w[0]; Bs[buf][lk4+1][lr] = w[1];
        Bs[buf][lk4+2][lr] = w[2]; Bs[buf][lk4+3][lr] = w[3];
        Bs[buf][16+lk4+0][lr] = w[4]; Bs[buf][16+lk4+1][lr] = w[5];
        Bs[buf][16+lk4+2][lr] = w[6]; Bs[buf][16+lk4+3][lr] = w[7];
        __syncthreads();

        if (c + 1 < nst) {
            const int k0n = (c + 1) << 5;
            av0 = *(const float4*)(Ab + (long long)lr * K + k0n + lk4);
            gen_w4(muRow, vRow, k0n + lk4, eBase, wk0, wk1, w);
            if (k0n + 32 <= K) {
                av1 = *(const float4*)(Ab + (long long)lr * K + k0n + 16 + lk4);
                gen_w4(muRow, vRow, k0n + 16 + lk4, eBase, wk0, wk1, w + 4);
            } else {
                av1 = make_float4(0.f, 0.f, 0.f, 0.f);
                w[4] = w[5] = w[6] = w[7] = 0.f;
            }
        }

        // MMA over stage c: 4 k8-steps x 4 n8-tiles, 2-term (A split, B pre-rounded)
#pragma unroll
        for (int ks = 0; ks < 4; ks++) {
            const int kb = ks * 8;
            float a0f = As[buf][kb + ka    ][m0 + ra    ];
            float a1f = As[buf][kb + ka    ][m0 + ra + 8];
            float a2f = As[buf][kb + ka + 4][m0 + ra    ];
            float a3f = As[buf][kb + ka + 4][m0 + ra + 8];
            uint32_t ah0, al0, ah1, al1, ah2, al2, ah3, al3;
            tf32_split(a0f, ah0, al0); tf32_split(a1f, ah1, al1);
            tf32_split(a2f, ah2, al2); tf32_split(a3f, ah3, al3);
#pragma unroll
            for (int tj = 0; tj < 4; tj++) {
                uint32_t b0 = __float_as_uint(Bs[buf][kb + ka    ][n0b + tj * 8 + ra]);
                uint32_t b1 = __float_as_uint(Bs[buf][kb + ka + 4][n0b + tj * 8 + ra]);
                mma_tf32(acc[tj], al0, al1, al2, al3, b0, b1);  // alo*b
                mma_tf32(acc[tj], ah0, ah1, ah2, ah3, b0, b1);  // ahi*b
            }
        }
    }

    // ---- epilogue: fragment layout -> gmem, +bias, relu ----
    const int row0 = m0 + ra;
    const int row1 = m0 + ra + 8;
#pragma unroll
    for (int tj = 0; tj < 4; tj++) {
        int n = n0b + tj * 8 + 2 * ka;
        float bb0 = bias_s[n], bb1 = bias_s[n + 1];
        float v00 = acc[tj][0] + bb0, v01 = acc[tj][1] + bb1;
        float v10 = acc[tj][2] + bb0, v11 = acc[tj][3] + bb1;
        if (relu) {
            v00 = fmaxf(v00, 0.f); v01 = fmaxf(v01, 0.f);
            v10 = fmaxf(v10, 0.f); v11 = fmaxf(v11, 0.f);
        }
        float* p0 = C + ((long long)s * 64 + row0) * N + nblk * 64 + n;
        float* p1 = C + ((long long)s * 64 + row1) * N + nblk * 64 + n;
        *(float2*)p0 = make_float2(v00, v01);
        *(float2*)p1 = make_float2(v10, v11);
    }
}

// ---------------- final layer: 2 blocks per sample, gen partitioned by output-half --------
__global__ __launch_bounds__(256) void layer3_fused(
    const float* __restrict__ H,
    const float* __restrict__ muW, const float* __restrict__ vW,
    const float* __restrict__ mub, const float* __restrict__ vb,
    float* __restrict__ out,
    uint32_t wk0, uint32_t wk1, uint32_t bk0, uint32_t bk1)
{
    const int s = blockIdx.x;
    const int h = blockIdx.y;
    const int t = threadIdx.x;
    __shared__ float Ws[5 * D_H];
    __shared__ float bsm[5];

#pragma unroll
    for (int i = 0; i < (5 * D_H) / 256; i++) {
        int j = t + 256 * i;
        uint32_t e = (uint32_t)(s * (D_OUT * D_H) + h * (5 * D_H) + j);
        uint2 r = threefry2x32_dev(wk0, wk1, 0u, e);
        int jg = h * (5 * D_H) + j;
        Ws[j] = __fmaf_rn(__expf(vW[jg]), jax_normal_fast(r.x ^ r.y), muW[jg]);
    }
    if (t < 5) {
        int og = h * 5 + t;
        uint2 r = threefry2x32_dev(bk0, bk1, 0u, (uint32_t)(s * D_OUT + og));
        bsm[t] = __fmaf_rn(__expf(vb[og]), jax_normal_fast(r.x ^ r.y), mub[og]);
    }
    __syncthreads();

    const int w = t >> 5, l = t & 31;
#pragma unroll
    for (int ri = 0; ri < 8; ri++) {
        int b = w * 8 + ri;
        const float* Hb = H + ((long long)s * BATCH + b) * D_H;
        float hh[16];
#pragma unroll
        for (int i = 0; i < 16; i++) hh[i] = Hb[l + 32 * i];
#pragma unroll
        for (int o = 0; o < 5; o++) {
            float acc = 0.0f;
#pragma unroll
            for (int i = 0; i < 16; i++)
                acc = __fmaf_rn(hh[i], Ws[o * D_H + l + 32 * i], acc);
            acc += __shfl_xor_sync(0xffffffffu, acc, 16);
            acc += __shfl_xor_sync(0xffffffffu, acc, 8);
            acc += __shfl_xor_sync(0xffffffffu, acc, 4);
            acc += __shfl_xor_sync(0xffffffffu, acc, 2);
            acc += __shfl_xor_sync(0xffffffffu, acc, 1);
            if (l == 0)
                out[((long long)s * BATCH + b) * D_OUT + h * 5 + o] = acc + bsm[o];
        }
    }
}

// ---------------- host-side threefry (subkey derivation) ----------------
static inline uint32_t h_rotl(uint32_t x, int r) { return (x << r) | (x >> (32 - r)); }
static void tf_host(uint32_t k0, uint32_t k1, uint32_t x0, uint32_t x1,
                    uint32_t* o0, uint32_t* o1) {
    uint32_t k2 = k0 ^ k1 ^ 0x1BD11BDAu;
    x0 += k0; x1 += k1;
    static const int R[2][4] = {{13,15,26,6},{17,29,16,24}};
    const uint32_t ks[3] = {k0, k1, k2};
    for (int i = 0; i < 5; i++) {
        for (int r = 0; r < 4; r++) {
            x0 += x1; x1 = h_rotl(x1, R[i & 1][r]); x1 ^= x0;
        }
        x0 += ks[(i + 1) % 3];
        x1 += ks[(i + 2) % 3] + (uint32_t)(i + 1);
    }
    *o0 = x0; *o1 = x1;
}

extern "C" void kernel_launch(void* const* d_in, const int* in_sizes, int n_in,
                              void* d_out, int out_size) {
    const float* x    = (const float*)d_in[0];
    const float* muW0 = (const float*)d_in[1];
    const float* mub0 = (const float*)d_in[2];
    const float* muW1 = (const float*)d_in[3];
    const float* mub1 = (const float*)d_in[4];
    const float* muW2 = (const float*)d_in[5];
    const float* mub2 = (const float*)d_in[6];
    const float* muW3 = (const float*)d_in[7];
    const float* mub3 = (const float*)d_in[8];
    const float* vW0  = (const float*)d_in[9];
    const float* vb0  = (const float*)d_in[10];
    const float* vW1  = (const float*)d_in[11];
    const float* vb1  = (const float*)d_in[12];
    const float* vW2  = (const float*)d_in[13];
    const float* vb2  = (const float*)d_in[14];
    const float* vW3  = (const float*)d_in[15];
    const float* vb3  = (const float*)d_in[16];
    float* out = (float*)d_out;

    uint32_t kk[8][2];
    for (int i = 0; i < 8; i++) tf_host(0u, 1u, 0u, (uint32_t)i, &kk[i][0], &kk[i][1]);

    float *pH1, *pH2, *pH3;
    cudaGetSymbolAddress((void**)&pH1, g_H1);
    cudaGetSymbolAddress((void**)&pH2, g_H2);
    cudaGetSymbolAddress((void**)&pH3, g_H3);

    fused_layer<<<dim3(D_H/64, NSAMP), 256>>>(x,   0,
                                              muW0, vW0, mub0, vb0,
                                              pH1, D_IN, D_H, 1,
                                              kk[0][0], kk[0][1], kk[1][0], kk[1][1]);
    fused_layer<<<dim3(D_H/64, NSAMP), 256>>>(pH1, (long long)BATCH*D_H,
                                              muW1, vW1, mub1, vb1,
                                              pH2, D_H, D_H, 1,
                                              kk[2][0], kk[2][1], kk[3][0], kk[3][1]);
    fused_layer<<<dim3(D_H/64, NSAMP), 256>>>(pH2, (long long)BATCH*D_H,
                                              muW2, vW2, mub2, vb2,
                                              pH3, D_H, D_H, 1,
                                              kk[4][0], kk[4][1], kk[5][0], kk[5][1]);
    layer3_fused<<<dim3(NSAMP, 2), 256>>>(pH3, muW3, vW3, mub3, vb3, out,
                                          kk[6][0], kk[6][1], kk[7][0], kk[7][1]);
}

// round 10
// speedup vs baseline: 1.3630x; 1.0945x over previous
#include <cuda_runtime.h>
#include <stdint.h>

#define NSAMP 150
#define D_IN  784
#define D_H   512
#define D_OUT 10
#define BATCH 64

// ---------------- device scratch: activations only ----------------
__device__ __align__(16) float g_X [BATCH * D_IN];          // tf32-rounded x
__device__ __align__(16) float g_H1[NSAMP * BATCH * D_H];   // tf32-rounded
__device__ __align__(16) float g_H2[NSAMP * BATCH * D_H];   // tf32-rounded
__device__ __align__(16) float g_H3[NSAMP * BATCH * D_H];   // fp32 (layer3 input)

// ---------------- tf32 helpers ----------------
__device__ __forceinline__ float tf32_round(float a) {
    uint32_t h;
    asm("cvt.rna.tf32.f32 %0, %1;" : "=r"(h) : "f"(a));
    return __uint_as_float(h);
}
__device__ __forceinline__ void mma_tf32(float* c,
                                         uint32_t a0, uint32_t a1, uint32_t a2, uint32_t a3,
                                         uint32_t b0, uint32_t b1) {
    asm("mma.sync.aligned.m16n8k8.row.col.f32.tf32.tf32.f32 "
        "{%0,%1,%2,%3}, {%4,%5,%6,%7}, {%8,%9}, {%0,%1,%2,%3};"
        : "+f"(c[0]), "+f"(c[1]), "+f"(c[2]), "+f"(c[3])
        : "r"(a0), "r"(a1), "r"(a2), "r"(a3), "r"(b0), "r"(b1));
}

// ---------------- threefry2x32 (20 rounds), bit-exact vs jax._src.prng ----------------
__device__ __forceinline__ void tf_round(uint32_t& x0, uint32_t& x1, int r) {
    x0 += x1;
    x1 = __funnelshift_l(x1, x1, r);
    x1 ^= x0;
}
__device__ __forceinline__ uint2 threefry2x32_dev(uint32_t k0, uint32_t k1,
                                                  uint32_t x0, uint32_t x1) {
    uint32_t k2 = k0 ^ k1 ^ 0x1BD11BDAu;
    x0 += k0; x1 += k1;
    tf_round(x0,x1,13); tf_round(x0,x1,15); tf_round(x0,x1,26); tf_round(x0,x1,6);
    x0 += k1; x1 += k2 + 1u;
    tf_round(x0,x1,17); tf_round(x0,x1,29); tf_round(x0,x1,16); tf_round(x0,x1,24);
    x0 += k2; x1 += k0 + 2u;
    tf_round(x0,x1,13); tf_round(x0,x1,15); tf_round(x0,x1,26); tf_round(x0,x1,6);
    x0 += k0; x1 += k1 + 3u;
    tf_round(x0,x1,17); tf_round(x0,x1,29); tf_round(x0,x1,16); tf_round(x0,x1,24);
    x0 += k1; x1 += k2 + 4u;
    tf_round(x0,x1,13); tf_round(x0,x1,15); tf_round(x0,x1,26); tf_round(x0,x1,6);
    x0 += k2; x1 += k0 + 5u;
    return make_uint2(x0, x1);
}

// ---------------- bits -> N(0,1): fast-math clone of XLA pipeline ----------------
__device__ __forceinline__ float jax_normal_fast(uint32_t bits) {
    const float LO = -0.99999994039535522461f;
    float f = __uint_as_float((bits >> 9) | 0x3f800000u) - 1.0f;
    float x = fmaxf(__fmaf_rn(f, 2.0f, LO), LO);
    float y = x * x;
    float t = 1.0f - y;
    float w = (t == 1.0f) ? y : -__logf(t);
    float p;
    if (w < 5.0f) {
        float ww = w - 2.5f;
        p =                2.81022636e-08f;
        p = __fmaf_rn(p, ww, 3.43273939e-07f);
        p = __fmaf_rn(p, ww, -3.5233877e-06f);
        p = __fmaf_rn(p, ww, -4.39150654e-06f);
        p = __fmaf_rn(p, ww, 0.00021858087f);
        p = __fmaf_rn(p, ww, -0.00125372503f);
        p = __fmaf_rn(p, ww, -0.00417768164f);
        p = __fmaf_rn(p, ww, 0.246640727f);
        p = __fmaf_rn(p, ww, 1.50140941f);
    } else {
        float ww = __fsqrt_rn(w) - 3.0f;
        p =                -0.000200214257f;
        p = __fmaf_rn(p, ww, 0.000100950558f);
        p = __fmaf_rn(p, ww, 0.00134934322f);
        p = __fmaf_rn(p, ww, -0.00367342844f);
        p = __fmaf_rn(p, ww, 0.00573950773f);
        p = __fmaf_rn(p, ww, -0.0076224613f);
        p = __fmaf_rn(p, ww, 0.00943887047f);
        p = __fmaf_rn(p, ww, 1.00167406f);
        p = __fmaf_rn(p, ww, 2.83297682f);
    }
    return 1.4142135623730951f * (p * x);
}

// gen 4 weights at k = kk..kk+3 (row n_glob), tf32-rounded
__device__ __forceinline__ void gen_w4(const float* __restrict__ muRow,
                                       const float* __restrict__ vRow,
                                       int kk, uint32_t eBase,
                                       uint32_t wk0, uint32_t wk1, float* w) {
    float4 mv = *(const float4*)(muRow + kk);
    float4 vv = *(const float4*)(vRow  + kk);
    uint32_t e0 = eBase + (uint32_t)kk;
    uint2 r0 = threefry2x32_dev(wk0, wk1, 0u, e0 + 0);
    uint2 r1 = threefry2x32_dev(wk0, wk1, 0u, e0 + 1);
    uint2 r2 = threefry2x32_dev(wk0, wk1, 0u, e0 + 2);
    uint2 r3 = threefry2x32_dev(wk0, wk1, 0u, e0 + 3);
    w[0] = tf32_round(__fmaf_rn(__expf(vv.x), jax_normal_fast(r0.x ^ r0.y), mv.x));
    w[1] = tf32_round(__fmaf_rn(__expf(vv.y), jax_normal_fast(r1.x ^ r1.y), mv.y));
    w[2] = tf32_round(__fmaf_rn(__expf(vv.z), jax_normal_fast(r2.x ^ r2.y), mv.z));
    w[3] = tf32_round(__fmaf_rn(__expf(vv.w), jax_normal_fast(r3.x ^ r3.y), mv.w));
}

// ---------------- tiny pre-kernel: round x to tf32 ----------------
__global__ void round_x(const float* __restrict__ x, float* __restrict__ xr, int n) {
    int i = blockIdx.x * blockDim.x + threadIdx.x;
    if (i < n) xr[i] = tf32_round(x[i]);
}

// ---------------- fused layer: 64x64 tile, 32k stages, 1 barrier/stage, 1-term tf32 -------
// A is pre-rounded to tf32; W rounded at gen. C = relu(A @ W^T + b), optionally tf32-rounded.
__global__ __launch_bounds__(256, 3) void fused_layer(
    const float* __restrict__ A, long long strideA,
    const float* __restrict__ muW, const float* __restrict__ vW,
    const float* __restrict__ mub, const float* __restrict__ vb,
    float* __restrict__ C, int K, int N, int relu, int round_out,
    uint32_t wk0, uint32_t wk1, uint32_t bk0, uint32_t bk1)
{
    const int s    = blockIdx.y;
    const int nblk = blockIdx.x;
    const int t    = threadIdx.x;      // 256

    __shared__ float As[2][32][68];    // [buf][k][m]  (tf32 values)
    __shared__ float Bs[2][32][68];    // [buf][k][n]  (tf32 values)
    __shared__ float bias_s[64];

    const int lr   = t >> 2;           // 0..63 row (A-row / W-row) producer
    const int lk4  = (t & 3) << 2;     // k offset 0,4,8,12 within 16-k half
    const int lane = t & 31;
    const int wrp  = t >> 5;           // 0..7
    const int m0   = (wrp & 3) * 16;
    const int n0b  = (wrp >> 2) * 32;
    const int ka   = lane & 3;
    const int ra   = lane >> 2;

    const float* Ab     = A + (long long)s * strideA;
    const int    n_glob = nblk * 64 + lr;
    const float* muRow  = muW + (long long)n_glob * K;
    const float* vRow   = vW  + (long long)n_glob * K;
    const uint32_t eBase = ((uint32_t)s * (uint32_t)N + (uint32_t)n_glob) * (uint32_t)K;

    if (t < 64) {
        int nb = nblk * 64 + t;
        uint2 r = threefry2x32_dev(bk0, bk1, 0u, (uint32_t)(s * N + nb));
        bias_s[t] = __fmaf_rn(__expf(vb[nb]), jax_normal_fast(r.x ^ r.y), mub[nb]);
    }

    const int nst = (K + 31) >> 5;     // 32-k stages (last half-stage zero-padded)

    // ---- prologue: load + gen stage 0 ----
    float4 av0, av1;
    float  w[8];
    {
        av0 = *(const float4*)(Ab + (long long)lr * K + lk4);
        gen_w4(muRow, vRow, lk4, eBase, wk0, wk1, w);
        if (32 <= K) {
            av1 = *(const float4*)(Ab + (long long)lr * K + 16 + lk4);
            gen_w4(muRow, vRow, 16 + lk4, eBase, wk0, wk1, w + 4);
        } else {
            av1 = make_float4(0.f, 0.f, 0.f, 0.f);
            w[4] = w[5] = w[6] = w[7] = 0.f;
        }
    }

    float acc[4][4];
#pragma unroll
    for (int i = 0; i < 4; i++)
#pragma unroll
        for (int j = 0; j < 4; j++) acc[i][j] = 0.0f;

    // ---- main loop: store(c) | sync | gen(c+1) | MMA(c) ----
    for (int c = 0; c < nst; c++) {
        const int buf = c & 1;
        As[buf][lk4+0][lr] = av0.x; As[buf][lk4+1][lr] = av0.y;
        As[buf][lk4+2][lr] = av0.z; As[buf][lk4+3][lr] = av0.w;
        As[buf][16+lk4+0][lr] = av1.x; As[buf][16+lk4+1][lr] = av1.y;
        As[buf][16+lk4+2][lr] = av1.z; As[buf][16+lk4+3][lr] = av1.w;
        Bs[buf][lk4+0][lr] = w[0]; Bs[buf][lk4+1][lr] = w[1];
        Bs[buf][lk4+2][lr] = w[2]; Bs[buf][lk4+3][lr] = w[3];
        Bs[buf][16+lk4+0][lr] = w[4]; Bs[buf][16+lk4+1][lr] = w[5];
        Bs[buf][16+lk4+2][lr] = w[6]; Bs[buf][16+lk4+3][lr] = w[7];
        __syncthreads();

        if (c + 1 < nst) {
            const int k0n = (c + 1) << 5;
            av0 = *(const float4*)(Ab + (long long)lr * K + k0n + lk4);
            gen_w4(muRow, vRow, k0n + lk4, eBase, wk0, wk1, w);
            if (k0n + 32 <= K) {
                av1 = *(const float4*)(Ab + (long long)lr * K + k0n + 16 + lk4);
                gen_w4(muRow, vRow, k0n + 16 + lk4, eBase, wk0, wk1, w + 4);
            } else {
                av1 = make_float4(0.f, 0.f, 0.f, 0.f);
                w[4] = w[5] = w[6] = w[7] = 0.f;
            }
        }

        // MMA over stage c: 4 k8-steps x 4 n8-tiles, 1-term (A & B both tf32)
#pragma unroll
        for (int ks = 0; ks < 4; ks++) {
            const int kb = ks * 8;
            uint32_t a0 = __float_as_uint(As[buf][kb + ka    ][m0 + ra    ]);
            uint32_t a1 = __float_as_uint(As[buf][kb + ka    ][m0 + ra + 8]);
            uint32_t a2 = __float_as_uint(As[buf][kb + ka + 4][m0 + ra    ]);
            uint32_t a3 = __float_as_uint(As[buf][kb + ka + 4][m0 + ra + 8]);
#pragma unroll
            for (int tj = 0; tj < 4; tj++) {
                uint32_t b0 = __float_as_uint(Bs[buf][kb + ka    ][n0b + tj * 8 + ra]);
                uint32_t b1 = __float_as_uint(Bs[buf][kb + ka + 4][n0b + tj * 8 + ra]);
                mma_tf32(acc[tj], a0, a1, a2, a3, b0, b1);
            }
        }
    }

    // ---- epilogue: +bias, relu, optional tf32 round, store ----
    const int row0 = m0 + ra;
    const int row1 = m0 + ra + 8;
#pragma unroll
    for (int tj = 0; tj < 4; tj++) {
        int n = n0b + tj * 8 + 2 * ka;
        float bb0 = bias_s[n], bb1 = bias_s[n + 1];
        float v00 = acc[tj][0] + bb0, v01 = acc[tj][1] + bb1;
        float v10 = acc[tj][2] + bb0, v11 = acc[tj][3] + bb1;
        if (relu) {
            v00 = fmaxf(v00, 0.f); v01 = fmaxf(v01, 0.f);
            v10 = fmaxf(v10, 0.f); v11 = fmaxf(v11, 0.f);
        }
        if (round_out) {
            v00 = tf32_round(v00); v01 = tf32_round(v01);
            v10 = tf32_round(v10); v11 = tf32_round(v11);
        }
        float* p0 = C + ((long long)s * 64 + row0) * N + nblk * 64 + n;
        float* p1 = C + ((long long)s * 64 + row1) * N + nblk * 64 + n;
        *(float2*)p0 = make_float2(v00, v01);
        *(float2*)p1 = make_float2(v10, v11);
    }
}

// ---------------- final layer: 2 blocks per sample, gen partitioned by output-half --------
__global__ __launch_bounds__(256) void layer3_fused(
    const float* __restrict__ H,
    const float* __restrict__ muW, const float* __restrict__ vW,
    const float* __restrict__ mub, const float* __restrict__ vb,
    float* __restrict__ out,
    uint32_t wk0, uint32_t wk1, uint32_t bk0, uint32_t bk1)
{
    const int s = blockIdx.x;
    const int h = blockIdx.y;
    const int t = threadIdx.x;
    __shared__ float Ws[5 * D_H];
    __shared__ float bsm[5];

#pragma unroll
    for (int i = 0; i < (5 * D_H) / 256; i++) {
        int j = t + 256 * i;
        uint32_t e = (uint32_t)(s * (D_OUT * D_H) + h * (5 * D_H) + j);
        uint2 r = threefry2x32_dev(wk0, wk1, 0u, e);
        int jg = h * (5 * D_H) + j;
        Ws[j] = __fmaf_rn(__expf(vW[jg]), jax_normal_fast(r.x ^ r.y), muW[jg]);
    }
    if (t < 5) {
        int og = h * 5 + t;
        uint2 r = threefry2x32_dev(bk0, bk1, 0u, (uint32_t)(s * D_OUT + og));
        bsm[t] = __fmaf_rn(__expf(vb[og]), jax_normal_fast(r.x ^ r.y), mub[og]);
    }
    __syncthreads();

    const int w = t >> 5, l = t & 31;
#pragma unroll
    for (int ri = 0; ri < 8; ri++) {
        int b = w * 8 + ri;
        const float* Hb = H + ((long long)s * BATCH + b) * D_H;
        float hh[16];
#pragma unroll
        for (int i = 0; i < 16; i++) hh[i] = Hb[l + 32 * i];
#pragma unroll
        for (int o = 0; o < 5; o++) {
            float acc = 0.0f;
#pragma unroll
            for (int i = 0; i < 16; i++)
                acc = __fmaf_rn(hh[i], Ws[o * D_H + l + 32 * i], acc);
            acc += __shfl_xor_sync(0xffffffffu, acc, 16);
            acc += __shfl_xor_sync(0xffffffffu, acc, 8);
            acc += __shfl_xor_sync(0xffffffffu, acc, 4);
            acc += __shfl_xor_sync(0xffffffffu, acc, 2);
            acc += __shfl_xor_sync(0xffffffffu, acc, 1);
            if (l == 0)
                out[((long long)s * BATCH + b) * D_OUT + h * 5 + o] = acc + bsm[o];
        }
    }
}

// ---------------- host-side threefry (subkey derivation) ----------------
static inline uint32_t h_rotl(uint32_t x, int r) { return (x << r) | (x >> (32 - r)); }
static void tf_host(uint32_t k0, uint32_t k1, uint32_t x0, uint32_t x1,
                    uint32_t* o0, uint32_t* o1) {
    uint32_t k2 = k0 ^ k1 ^ 0x1BD11BDAu;
    x0 += k0; x1 += k1;
    static const int R[2][4] = {{13,15,26,6},{17,29,16,24}};
    const uint32_t ks[3] = {k0, k1, k2};
    for (int i = 0; i < 5; i++) {
        for (int r = 0; r < 4; r++) {
            x0 += x1; x1 = h_rotl(x1, R[i & 1][r]); x1 ^= x0;
        }
        x0 += ks[(i + 1) % 3];
        x1 += ks[(i + 2) % 3] + (uint32_t)(i + 1);
    }
    *o0 = x0; *o1 = x1;
}

extern "C" void kernel_launch(void* const* d_in, const int* in_sizes, int n_in,
                              void* d_out, int out_size) {
    const float* x    = (const float*)d_in[0];
    const float* muW0 = (const float*)d_in[1];
    const float* mub0 = (const float*)d_in[2];
    const float* muW1 = (const float*)d_in[3];
    const float* mub1 = (const float*)d_in[4];
    const float* muW2 = (const float*)d_in[5];
    const float* mub2 = (const float*)d_in[6];
    const float* muW3 = (const float*)d_in[7];
    const float* mub3 = (const float*)d_in[8];
    const float* vW0  = (const float*)d_in[9];
    const float* vb0  = (const float*)d_in[10];
    const float* vW1  = (const float*)d_in[11];
    const float* vb1  = (const float*)d_in[12];
    const float* vW2  = (const float*)d_in[13];
    const float* vb2  = (const float*)d_in[14];
    const float* vW3  = (const float*)d_in[15];
    const float* vb3  = (const float*)d_in[16];
    float* out = (float*)d_out;

    uint32_t kk[8][2];
    for (int i = 0; i < 8; i++) tf_host(0u, 1u, 0u, (uint32_t)i, &kk[i][0], &kk[i][1]);

    float *pX, *pH1, *pH2, *pH3;
    cudaGetSymbolAddress((void**)&pX,  g_X);
    cudaGetSymbolAddress((void**)&pH1, g_H1);
    cudaGetSymbolAddress((void**)&pH2, g_H2);
    cudaGetSymbolAddress((void**)&pH3, g_H3);

    round_x<<<(BATCH * D_IN + 255) / 256, 256>>>(x, pX, BATCH * D_IN);

    fused_layer<<<dim3(D_H/64, NSAMP), 256>>>(pX,  0,
                                              muW0, vW0, mub0, vb0,
                                              pH1, D_IN, D_H, 1, 1,
                                              kk[0][0], kk[0][1], kk[1][0], kk[1][1]);
    fused_layer<<<dim3(D_H/64, NSAMP), 256>>>(pH1, (long long)BATCH*D_H,
                                              muW1, vW1, mub1, vb1,
                                              pH2, D_H, D_H, 1, 1,
                                              kk[2][0], kk[2][1], kk[3][0], kk[3][1]);
    fused_layer<<<dim3(D_H/64, NSAMP), 256>>>(pH2, (long long)BATCH*D_H,
                                              muW2, vW2, mub2, vb2,
                                              pH3, D_H, D_H, 1, 0,
                                              kk[4][0], kk[4][1], kk[5][0], kk[5][1]);
    layer3_fused<<<dim3(NSAMP, 2), 256>>>(pH3, muW3, vW3, mub3, vb3, out,
                                          kk[6][0], kk[6][1], kk[7][0], kk[7][1]);
}

// round 11
// speedup vs baseline: 1.3792x; 1.0119x over previous
#include <cuda_runtime.h>
#include <stdint.h>

#define NSAMP 150
#define D_IN  784
#define D_H   512
#define D_OUT 10
#define BATCH 64

// ---------------- device scratch: activations only ----------------
__device__ __align__(16) float g_X [BATCH * D_IN];          // tf32-rounded x
__device__ __align__(16) float g_H1[NSAMP * BATCH * D_H];   // tf32-rounded
__device__ __align__(16) float g_H2[NSAMP * BATCH * D_H];   // tf32-rounded
__device__ __align__(16) float g_H3[NSAMP * BATCH * D_H];   // fp32 (layer3 input)

// ---------------- tf32 helpers ----------------
__device__ __forceinline__ float tf32_round(float a) {
    uint32_t h;
    asm("cvt.rna.tf32.f32 %0, %1;" : "=r"(h) : "f"(a));
    return __uint_as_float(h);
}
__device__ __forceinline__ void mma_tf32(float* c,
                                         uint32_t a0, uint32_t a1, uint32_t a2, uint32_t a3,
                                         uint32_t b0, uint32_t b1) {
    asm("mma.sync.aligned.m16n8k8.row.col.f32.tf32.tf32.f32 "
        "{%0,%1,%2,%3}, {%4,%5,%6,%7}, {%8,%9}, {%0,%1,%2,%3};"
        : "+f"(c[0]), "+f"(c[1]), "+f"(c[2]), "+f"(c[3])
        : "r"(a0), "r"(a1), "r"(a2), "r"(a3), "r"(b0), "r"(b1));
}

// ---------------- threefry2x32 (20 rounds), bit-exact vs jax._src.prng ----------------
__device__ __forceinline__ void tf_round(uint32_t& x0, uint32_t& x1, int r) {
    x0 += x1;
    x1 = __funnelshift_l(x1, x1, r);
    x1 ^= x0;
}
__device__ __forceinline__ uint2 threefry2x32_dev(uint32_t k0, uint32_t k1,
                                                  uint32_t x0, uint32_t x1) {
    uint32_t k2 = k0 ^ k1 ^ 0x1BD11BDAu;
    x0 += k0; x1 += k1;
    tf_round(x0,x1,13); tf_round(x0,x1,15); tf_round(x0,x1,26); tf_round(x0,x1,6);
    x0 += k1; x1 += k2 + 1u;
    tf_round(x0,x1,17); tf_round(x0,x1,29); tf_round(x0,x1,16); tf_round(x0,x1,24);
    x0 += k2; x1 += k0 + 2u;
    tf_round(x0,x1,13); tf_round(x0,x1,15); tf_round(x0,x1,26); tf_round(x0,x1,6);
    x0 += k0; x1 += k1 + 3u;
    tf_round(x0,x1,17); tf_round(x0,x1,29); tf_round(x0,x1,16); tf_round(x0,x1,24);
    x0 += k1; x1 += k2 + 4u;
    tf_round(x0,x1,13); tf_round(x0,x1,15); tf_round(x0,x1,26); tf_round(x0,x1,6);
    x0 += k2; x1 += k0 + 5u;
    return make_uint2(x0, x1);
}

// ---------------- bits -> N(0,1): fast-math clone of XLA pipeline ----------------
__device__ __forceinline__ float jax_normal_fast(uint32_t bits) {
    const float LO = -0.99999994039535522461f;
    float f = __uint_as_float((bits >> 9) | 0x3f800000u) - 1.0f;
    float x = fmaxf(__fmaf_rn(f, 2.0f, LO), LO);
    float y = x * x;
    float t = 1.0f - y;
    float w = (t == 1.0f) ? y : -__logf(t);
    float p;
    if (w < 5.0f) {
        float ww = w - 2.5f;
        p =                2.81022636e-08f;
        p = __fmaf_rn(p, ww, 3.43273939e-07f);
        p = __fmaf_rn(p, ww, -3.5233877e-06f);
        p = __fmaf_rn(p, ww, -4.39150654e-06f);
        p = __fmaf_rn(p, ww, 0.00021858087f);
        p = __fmaf_rn(p, ww, -0.00125372503f);
        p = __fmaf_rn(p, ww, -0.00417768164f);
        p = __fmaf_rn(p, ww, 0.246640727f);
        p = __fmaf_rn(p, ww, 1.50140941f);
    } else {
        float ww = __fsqrt_rn(w) - 3.0f;
        p =                -0.000200214257f;
        p = __fmaf_rn(p, ww, 0.000100950558f);
        p = __fmaf_rn(p, ww, 0.00134934322f);
        p = __fmaf_rn(p, ww, -0.00367342844f);
        p = __fmaf_rn(p, ww, 0.00573950773f);
        p = __fmaf_rn(p, ww, -0.0076224613f);
        p = __fmaf_rn(p, ww, 0.00943887047f);
        p = __fmaf_rn(p, ww, 1.00167406f);
        p = __fmaf_rn(p, ww, 2.83297682f);
    }
    return 1.4142135623730951f * (p * x);
}

// gen 4 weights at k = kk..kk+3 (row n_glob), tf32-rounded
__device__ __forceinline__ void gen_w4(const float* __restrict__ muRow,
                                       const float* __restrict__ vRow,
                                       int kk, uint32_t eBase,
                                       uint32_t wk0, uint32_t wk1, float* w) {
    float4 mv = *(const float4*)(muRow + kk);
    float4 vv = *(const float4*)(vRow  + kk);
    uint32_t e0 = eBase + (uint32_t)kk;
    uint2 r0 = threefry2x32_dev(wk0, wk1, 0u, e0 + 0);
    uint2 r1 = threefry2x32_dev(wk0, wk1, 0u, e0 + 1);
    uint2 r2 = threefry2x32_dev(wk0, wk1, 0u, e0 + 2);
    uint2 r3 = threefry2x32_dev(wk0, wk1, 0u, e0 + 3);
    w[0] = tf32_round(__fmaf_rn(__expf(vv.x), jax_normal_fast(r0.x ^ r0.y), mv.x));
    w[1] = tf32_round(__fmaf_rn(__expf(vv.y), jax_normal_fast(r1.x ^ r1.y), mv.y));
    w[2] = tf32_round(__fmaf_rn(__expf(vv.z), jax_normal_fast(r2.x ^ r2.y), mv.z));
    w[3] = tf32_round(__fmaf_rn(__expf(vv.w), jax_normal_fast(r3.x ^ r3.y), mv.w));
}

// gen stage (32 k) directly into smem buffers (no register staging)
__device__ __forceinline__ void gen_stage(
    const float* __restrict__ Ab, const float* __restrict__ muRow,
    const float* __restrict__ vRow, int K, int k0,
    uint32_t eBase, uint32_t wk0, uint32_t wk1,
    float (*Asb)[68], float (*Bsb)[68], int lr, int lk4)
{
    float4 av0 = *(const float4*)(Ab + (long long)lr * K + k0 + lk4);
    float w[4];
    gen_w4(muRow, vRow, k0 + lk4, eBase, wk0, wk1, w);
    Asb[lk4+0][lr] = av0.x; Asb[lk4+1][lr] = av0.y;
    Asb[lk4+2][lr] = av0.z; Asb[lk4+3][lr] = av0.w;
    Bsb[lk4+0][lr] = w[0];  Bsb[lk4+1][lr] = w[1];
    Bsb[lk4+2][lr] = w[2];  Bsb[lk4+3][lr] = w[3];
    if (k0 + 32 <= K) {
        float4 av1 = *(const float4*)(Ab + (long long)lr * K + k0 + 16 + lk4);
        gen_w4(muRow, vRow, k0 + 16 + lk4, eBase, wk0, wk1, w);
        Asb[16+lk4+0][lr] = av1.x; Asb[16+lk4+1][lr] = av1.y;
        Asb[16+lk4+2][lr] = av1.z; Asb[16+lk4+3][lr] = av1.w;
        Bsb[16+lk4+0][lr] = w[0];  Bsb[16+lk4+1][lr] = w[1];
        Bsb[16+lk4+2][lr] = w[2];  Bsb[16+lk4+3][lr] = w[3];
    } else {
        Asb[16+lk4+0][lr] = 0.f; Asb[16+lk4+1][lr] = 0.f;
        Asb[16+lk4+2][lr] = 0.f; Asb[16+lk4+3][lr] = 0.f;
        Bsb[16+lk4+0][lr] = 0.f; Bsb[16+lk4+1][lr] = 0.f;
        Bsb[16+lk4+2][lr] = 0.f; Bsb[16+lk4+3][lr] = 0.f;
    }
}

// ---------------- tiny pre-kernel: round x to tf32 ----------------
__global__ void round_x(const float* __restrict__ x, float* __restrict__ xr, int n) {
    int i = blockIdx.x * blockDim.x + threadIdx.x;
    if (i < n) xr[i] = tf32_round(x[i]);
}

// ---------------- fused layer: 64x64 tile, 32k stages, 1 barrier/stage, 1-term tf32 -------
// A pre-rounded tf32; W rounded at gen. Direct-to-smem gen (no register double-buffer).
__global__ __launch_bounds__(256, 4) void fused_layer(
    const float* __restrict__ A, long long strideA,
    const float* __restrict__ muW, const float* __restrict__ vW,
    const float* __restrict__ mub, const float* __restrict__ vb,
    float* __restrict__ C, int K, int N, int relu, int round_out,
    uint32_t wk0, uint32_t wk1, uint32_t bk0, uint32_t bk1)
{
    const int s    = blockIdx.y;
    const int nblk = blockIdx.x;
    const int t    = threadIdx.x;      // 256

    __shared__ float As[2][32][68];    // [buf][k][m]  (tf32 values)
    __shared__ float Bs[2][32][68];    // [buf][k][n]  (tf32 values)
    __shared__ float bias_s[64];

    const int lr   = t >> 2;           // 0..63 row (A-row / W-row) producer
    const int lk4  = (t & 3) << 2;     // k offset 0,4,8,12 within 16-k half
    const int lane = t & 31;
    const int wrp  = t >> 5;           // 0..7
    const int m0   = (wrp & 3) * 16;
    const int n0b  = (wrp >> 2) * 32;
    const int ka   = lane & 3;
    const int ra   = lane >> 2;

    const float* Ab     = A + (long long)s * strideA;
    const int    n_glob = nblk * 64 + lr;
    const float* muRow  = muW + (long long)n_glob * K;
    const float* vRow   = vW  + (long long)n_glob * K;
    const uint32_t eBase = ((uint32_t)s * (uint32_t)N + (uint32_t)n_glob) * (uint32_t)K;

    if (t < 64) {
        int nb = nblk * 64 + t;
        uint2 r = threefry2x32_dev(bk0, bk1, 0u, (uint32_t)(s * N + nb));
        bias_s[t] = __fmaf_rn(__expf(vb[nb]), jax_normal_fast(r.x ^ r.y), mub[nb]);
    }

    const int nst = (K + 31) >> 5;     // 32-k stages (last half-stage zero-padded)

    // ---- prologue: gen stage 0 straight into buf 0 ----
    gen_stage(Ab, muRow, vRow, K, 0, eBase, wk0, wk1, As[0], Bs[0], lr, lk4);

    float acc[4][4];
#pragma unroll
    for (int i = 0; i < 4; i++)
#pragma unroll
        for (int j = 0; j < 4; j++) acc[i][j] = 0.0f;

    // ---- main loop: sync | gen(c+1)->buf^1 | MMA(c) from buf ----
    for (int c = 0; c < nst; c++) {
        __syncthreads();
        const int buf = c & 1;

        if (c + 1 < nst) {
            gen_stage(Ab, muRow, vRow, K, (c + 1) << 5, eBase, wk0, wk1,
                      As[buf ^ 1], Bs[buf ^ 1], lr, lk4);
        }

        // MMA over stage c: 4 k8-steps x 4 n8-tiles, 1-term (A & B both tf32)
#pragma unroll
        for (int ks = 0; ks < 4; ks++) {
            const int kb = ks * 8;
            uint32_t a0 = __float_as_uint(As[buf][kb + ka    ][m0 + ra    ]);
            uint32_t a1 = __float_as_uint(As[buf][kb + ka    ][m0 + ra + 8]);
            uint32_t a2 = __float_as_uint(As[buf][kb + ka + 4][m0 + ra    ]);
            uint32_t a3 = __float_as_uint(As[buf][kb + ka + 4][m0 + ra + 8]);
#pragma unroll
            for (int tj = 0; tj < 4; tj++) {
                uint32_t b0 = __float_as_uint(Bs[buf][kb + ka    ][n0b + tj * 8 + ra]);
                uint32_t b1 = __float_as_uint(Bs[buf][kb + ka + 4][n0b + tj * 8 + ra]);
                mma_tf32(acc[tj], a0, a1, a2, a3, b0, b1);
            }
        }
    }

    // ---- epilogue: +bias, relu, optional tf32 round, store ----
    const int row0 = m0 + ra;
    const int row1 = m0 + ra + 8;
#pragma unroll
    for (int tj = 0; tj < 4; tj++) {
        int n = n0b + tj * 8 + 2 * ka;
        float bb0 = bias_s[n], bb1 = bias_s[n + 1];
        float v00 = acc[tj][0] + bb0, v01 = acc[tj][1] + bb1;
        float v10 = acc[tj][2] + bb0, v11 = acc[tj][3] + bb1;
        if (relu) {
            v00 = fmaxf(v00, 0.f); v01 = fmaxf(v01, 0.f);
            v10 = fmaxf(v10, 0.f); v11 = fmaxf(v11, 0.f);
        }
        if (round_out) {
            v00 = tf32_round(v00); v01 = tf32_round(v01);
            v10 = tf32_round(v10); v11 = tf32_round(v11);
        }
        float* p0 = C + ((long long)s * 64 + row0) * N + nblk * 64 + n;
        float* p1 = C + ((long long)s * 64 + row1) * N + nblk * 64 + n;
        *(float2*)p0 = make_float2(v00, v01);
        *(float2*)p1 = make_float2(v10, v11);
    }
}

// ---------------- final layer: 2 blocks per sample, gen partitioned by output-half --------
__global__ __launch_bounds__(256) void layer3_fused(
    const float* __restrict__ H,
    const float* __restrict__ muW, const float* __restrict__ vW,
    const float* __restrict__ mub, const float* __restrict__ vb,
    float* __restrict__ out,
    uint32_t wk0, uint32_t wk1, uint32_t bk0, uint32_t bk1)
{
    const int s = blockIdx.x;
    const int h = blockIdx.y;
    const int t = threadIdx.x;
    __shared__ float Ws[5 * D_H];
    __shared__ float bsm[5];

#pragma unroll
    for (int i = 0; i < (5 * D_H) / 256; i++) {
        int j = t + 256 * i;
        uint32_t e = (uint32_t)(s * (D_OUT * D_H) + h * (5 * D_H) + j);
        uint2 r = threefry2x32_dev(wk0, wk1, 0u, e);
        int jg = h * (5 * D_H) + j;
        Ws[j] = __fmaf_rn(__expf(vW[jg]), jax_normal_fast(r.x ^ r.y), muW[jg]);
    }
    if (t < 5) {
        int og = h * 5 + t;
        uint2 r = threefry2x32_dev(bk0, bk1, 0u, (uint32_t)(s * D_OUT + og));
        bsm[t] = __fmaf_rn(__expf(vb[og]), jax_normal_fast(r.x ^ r.y), mub[og]);
    }
    __syncthreads();

    const int w = t >> 5, l = t & 31;
#pragma unroll
    for (int ri = 0; ri < 8; ri++) {
        int b = w * 8 + ri;
        const float* Hb = H + ((long long)s * BATCH + b) * D_H;
        float hh[16];
#pragma unroll
        for (int i = 0; i < 16; i++) hh[i] = Hb[l + 32 * i];
#pragma unroll
        for (int o = 0; o < 5; o++) {
            float acc = 0.0f;
#pragma unroll
            for (int i = 0; i < 16; i++)
                acc = __fmaf_rn(hh[i], Ws[o * D_H + l + 32 * i], acc);
            acc += __shfl_xor_sync(0xffffffffu, acc, 16);
            acc += __shfl_xor_sync(0xffffffffu, acc, 8);
            acc += __shfl_xor_sync(0xffffffffu, acc, 4);
            acc += __shfl_xor_sync(0xffffffffu, acc, 2);
            acc += __shfl_xor_sync(0xffffffffu, acc, 1);
            if (l == 0)
                out[((long long)s * BATCH + b) * D_OUT + h * 5 + o] = acc + bsm[o];
        }
    }
}

// ---------------- host-side threefry (subkey derivation) ----------------
static inline uint32_t h_rotl(uint32_t x, int r) { return (x << r) | (x >> (32 - r)); }
static void tf_host(uint32_t k0, uint32_t k1, uint32_t x0, uint32_t x1,
                    uint32_t* o0, uint32_t* o1) {
    uint32_t k2 = k0 ^ k1 ^ 0x1BD11BDAu;
    x0 += k0; x1 += k1;
    static const int R[2][4] = {{13,15,26,6},{17,29,16,24}};
    const uint32_t ks[3] = {k0, k1, k2};
    for (int i = 0; i < 5; i++) {
        for (int r = 0; r < 4; r++) {
            x0 += x1; x1 = h_rotl(x1, R[i & 1][r]); x1 ^= x0;
        }
        x0 += ks[(i + 1) % 3];
        x1 += ks[(i + 2) % 3] + (uint32_t)(i + 1);
    }
    *o0 = x0; *o1 = x1;
}

extern "C" void kernel_launch(void* const* d_in, const int* in_sizes, int n_in,
                              void* d_out, int out_size) {
    const float* x    = (const float*)d_in[0];
    const float* muW0 = (const float*)d_in[1];
    const float* mub0 = (const float*)d_in[2];
    const float* muW1 = (const float*)d_in[3];
    const float* mub1 = (const float*)d_in[4];
    const float* muW2 = (const float*)d_in[5];
    const float* mub2 = (const float*)d_in[6];
    const float* muW3 = (const float*)d_in[7];
    const float* mub3 = (const float*)d_in[8];
    const float* vW0  = (const float*)d_in[9];
    const float* vb0  = (const float*)d_in[10];
    const float* vW1  = (const float*)d_in[11];
    const float* vb1  = (const float*)d_in[12];
    const float* vW2  = (const float*)d_in[13];
    const float* vb2  = (const float*)d_in[14];
    const float* vW3  = (const float*)d_in[15];
    const float* vb3  = (const float*)d_in[16];
    float* out = (float*)d_out;

    uint32_t kk[8][2];
    for (int i = 0; i < 8; i++) tf_host(0u, 1u, 0u, (uint32_t)i, &kk[i][0], &kk[i][1]);

    float *pX, *pH1, *pH2, *pH3;
    cudaGetSymbolAddress((void**)&pX,  g_X);
    cudaGetSymbolAddress((void**)&pH1, g_H1);
    cudaGetSymbolAddress((void**)&pH2, g_H2);
    cudaGetSymbolAddress((void**)&pH3, g_H3);

    round_x<<<(BATCH * D_IN + 255) / 256, 256>>>(x, pX, BATCH * D_IN);

    fused_layer<<<dim3(D_H/64, NSAMP), 256>>>(pX,  0,
                                              muW0, vW0, mub0, vb0,
                                              pH1, D_IN, D_H, 1, 1,
                                              kk[0][0], kk[0][1], kk[1][0], kk[1][1]);
    fused_layer<<<dim3(D_H/64, NSAMP), 256>>>(pH1, (long long)BATCH*D_H,
                                              muW1, vW1, mub1, vb1,
                                              pH2, D_H, D_H, 1, 1,
                                              kk[2][0], kk[2][1], kk[3][0], kk[3][1]);
    fused_layer<<<dim3(D_H/64, NSAMP), 256>>>(pH2, (long long)BATCH*D_H,
                                              muW2, vW2, mub2, vb2,
                                              pH3, D_H, D_H, 1, 0,
                                              kk[4][0], kk[4][1], kk[5][0], kk[5][1]);
    layer3_fused<<<dim3(NSAMP, 2), 256>>>(pH3, muW3, vW3, mub3, vb3, out,
                                          kk[6][0], kk[6][1], kk[7][0], kk[7][1]);
}

// round 12
// speedup vs baseline: 1.4001x; 1.0152x over previous
#include <cuda_runtime.h>
#include <stdint.h>

#define NSAMP 150
#define D_IN  784
#define D_H   512
#define D_OUT 10
#define BATCH 64

// ---------------- device scratch: activations only ----------------
__device__ __align__(16) float g_X [BATCH * D_IN];          // tf32-rounded x
__device__ __align__(16) float g_H1[NSAMP * BATCH * D_H];   // tf32-rounded
__device__ __align__(16) float g_H2[NSAMP * BATCH * D_H];   // tf32-rounded
__device__ __align__(16) float g_H3[NSAMP * BATCH * D_H];   // fp32 (layer3 input)

// ---------------- tf32 helpers ----------------
__device__ __forceinline__ float tf32_round(float a) {
    uint32_t h;
    asm("cvt.rna.tf32.f32 %0, %1;" : "=r"(h) : "f"(a));
    return __uint_as_float(h);
}
__device__ __forceinline__ void mma_tf32(float* c,
                                         uint32_t a0, uint32_t a1, uint32_t a2, uint32_t a3,
                                         uint32_t b0, uint32_t b1) {
    asm("mma.sync.aligned.m16n8k8.row.col.f32.tf32.tf32.f32 "
        "{%0,%1,%2,%3}, {%4,%5,%6,%7}, {%8,%9}, {%0,%1,%2,%3};"
        : "+f"(c[0]), "+f"(c[1]), "+f"(c[2]), "+f"(c[3])
        : "r"(a0), "r"(a1), "r"(a2), "r"(a3), "r"(b0), "r"(b1));
}

// ---------------- threefry2x32 (20 rounds), bit-exact vs jax._src.prng ----------------
// Adds routed to the FMA pipe as IMAD (mad.lo.u32 with runtime 'one') to offload the
// saturated ALU pipe (SHF/LOP3 stay there). 'one' comes from a kernel argument so
// ptxas cannot fold the IMAD back into IADD3.
__device__ __forceinline__ void imad_add(uint32_t& d, uint32_t a, uint32_t one) {
    asm("mad.lo.u32 %0, %1, %2, %0;" : "+r"(d) : "r"(a), "r"(one));
}
__device__ __forceinline__ void tf_round_m(uint32_t& x0, uint32_t& x1, int r, uint32_t one) {
    imad_add(x0, x1, one);                 // x0 += x1   (IMAD, fma pipe)
    x1 = __funnelshift_l(x1, x1, r);       // SHF        (alu pipe)
    x1 ^= x0;                              // LOP3       (alu pipe)
}
__device__ __forceinline__ uint2 threefry2x32_dev(uint32_t k0, uint32_t k1,
                                                  uint32_t x0, uint32_t x1,
                                                  uint32_t one) {
    uint32_t k2 = k0 ^ k1 ^ 0x1BD11BDAu;
    imad_add(x0, k0, one); x1 += k1;
    tf_round_m(x0,x1,13,one); tf_round_m(x0,x1,15,one); tf_round_m(x0,x1,26,one); tf_round_m(x0,x1,6,one);
    imad_add(x0, k1, one); x1 += k2 + 1u;
    tf_round_m(x0,x1,17,one); tf_round_m(x0,x1,29,one); tf_round_m(x0,x1,16,one); tf_round_m(x0,x1,24,one);
    imad_add(x0, k2, one); x1 += k0 + 2u;
    tf_round_m(x0,x1,13,one); tf_round_m(x0,x1,15,one); tf_round_m(x0,x1,26,one); tf_round_m(x0,x1,6,one);
    imad_add(x0, k0, one); x1 += k1 + 3u;
    tf_round_m(x0,x1,17,one); tf_round_m(x0,x1,29,one); tf_round_m(x0,x1,16,one); tf_round_m(x0,x1,24,one);
    imad_add(x0, k1, one); x1 += k2 + 4u;
    tf_round_m(x0,x1,13,one); tf_round_m(x0,x1,15,one); tf_round_m(x0,x1,26,one); tf_round_m(x0,x1,6,one);
    imad_add(x0, k2, one); x1 += k0 + 5u;
    return make_uint2(x0, x1);
}

// ---------------- bits -> N(0,1): fast-math clone of XLA pipeline ----------------
__device__ __forceinline__ float jax_normal_fast(uint32_t bits) {
    const float LO = -0.99999994039535522461f;
    float f = __uint_as_float((bits >> 9) | 0x3f800000u) - 1.0f;
    float x = fmaxf(__fmaf_rn(f, 2.0f, LO), LO);
    float y = x * x;
    float t = 1.0f - y;
    float w = (t == 1.0f) ? y : -__logf(t);
    float p;
    if (w < 5.0f) {
        float ww = w - 2.5f;
        p =                2.81022636e-08f;
        p = __fmaf_rn(p, ww, 3.43273939e-07f);
        p = __fmaf_rn(p, ww, -3.5233877e-06f);
        p = __fmaf_rn(p, ww, -4.39150654e-06f);
        p = __fmaf_rn(p, ww, 0.00021858087f);
        p = __fmaf_rn(p, ww, -0.00125372503f);
        p = __fmaf_rn(p, ww, -0.00417768164f);
        p = __fmaf_rn(p, ww, 0.246640727f);
        p = __fmaf_rn(p, ww, 1.50140941f);
    } else {
        float ww = __fsqrt_rn(w) - 3.0f;
        p =                -0.000200214257f;
        p = __fmaf_rn(p, ww, 0.000100950558f);
        p = __fmaf_rn(p, ww, 0.00134934322f);
        p = __fmaf_rn(p, ww, -0.00367342844f);
        p = __fmaf_rn(p, ww, 0.00573950773f);
        p = __fmaf_rn(p, ww, -0.0076224613f);
        p = __fmaf_rn(p, ww, 0.00943887047f);
        p = __fmaf_rn(p, ww, 1.00167406f);
        p = __fmaf_rn(p, ww, 2.83297682f);
    }
    return 1.4142135623730951f * (p * x);
}

// gen 4 weights at k = kk..kk+3 (row n_glob), tf32-rounded
__device__ __forceinline__ void gen_w4(const float* __restrict__ muRow,
                                       const float* __restrict__ vRow,
                                       int kk, uint32_t eBase,
                                       uint32_t wk0, uint32_t wk1, uint32_t one,
                                       float* w) {
    float4 mv = *(const float4*)(muRow + kk);
    float4 vv = *(const float4*)(vRow  + kk);
    uint32_t e0 = eBase + (uint32_t)kk;
    uint2 r0 = threefry2x32_dev(wk0, wk1, 0u, e0 + 0, one);
    uint2 r1 = threefry2x32_dev(wk0, wk1, 0u, e0 + 1, one);
    uint2 r2 = threefry2x32_dev(wk0, wk1, 0u, e0 + 2, one);
    uint2 r3 = threefry2x32_dev(wk0, wk1, 0u, e0 + 3, one);
    w[0] = tf32_round(__fmaf_rn(__expf(vv.x), jax_normal_fast(r0.x ^ r0.y), mv.x));
    w[1] = tf32_round(__fmaf_rn(__expf(vv.y), jax_normal_fast(r1.x ^ r1.y), mv.y));
    w[2] = tf32_round(__fmaf_rn(__expf(vv.z), jax_normal_fast(r2.x ^ r2.y), mv.z));
    w[3] = tf32_round(__fmaf_rn(__expf(vv.w), jax_normal_fast(r3.x ^ r3.y), mv.w));
}

// gen stage (32 k) directly into smem buffers (no register staging)
__device__ __forceinline__ void gen_stage(
    const float* __restrict__ Ab, const float* __restrict__ muRow,
    const float* __restrict__ vRow, int K, int k0,
    uint32_t eBase, uint32_t wk0, uint32_t wk1, uint32_t one,
    float (*Asb)[68], float (*Bsb)[68], int lr, int lk4)
{
    float4 av0 = *(const float4*)(Ab + (long long)lr * K + k0 + lk4);
    float w[4];
    gen_w4(muRow, vRow, k0 + lk4, eBase, wk0, wk1, one, w);
    Asb[lk4+0][lr] = av0.x; Asb[lk4+1][lr] = av0.y;
    Asb[lk4+2][lr] = av0.z; Asb[lk4+3][lr] = av0.w;
    Bsb[lk4+0][lr] = w[0];  Bsb[lk4+1][lr] = w[1];
    Bsb[lk4+2][lr] = w[2];  Bsb[lk4+3][lr] = w[3];
    if (k0 + 32 <= K) {
        float4 av1 = *(const float4*)(Ab + (long long)lr * K + k0 + 16 + lk4);
        gen_w4(muRow, vRow, k0 + 16 + lk4, eBase, wk0, wk1, one, w);
        Asb[16+lk4+0][lr] = av1.x; Asb[16+lk4+1][lr] = av1.y;
        Asb[16+lk4+2][lr] = av1.z; Asb[16+lk4+3][lr] = av1.w;
        Bsb[16+lk4+0][lr] = w[0];  Bsb[16+lk4+1][lr] = w[1];
        Bsb[16+lk4+2][lr] = w[2];  Bsb[16+lk4+3][lr] = w[3];
    } else {
        Asb[16+lk4+0][lr] = 0.f; Asb[16+lk4+1][lr] = 0.f;
        Asb[16+lk4+2][lr] = 0.f; Asb[16+lk4+3][lr] = 0.f;
        Bsb[16+lk4+0][lr] = 0.f; Bsb[16+lk4+1][lr] = 0.f;
        Bsb[16+lk4+2][lr] = 0.f; Bsb[16+lk4+3][lr] = 0.f;
    }
}

// ---------------- tiny pre-kernel: round x to tf32 ----------------
__global__ void round_x(const float* __restrict__ x, float* __restrict__ xr, int n) {
    int i = blockIdx.x * blockDim.x + threadIdx.x;
    if (i < n) xr[i] = tf32_round(x[i]);
}

// ---------------- fused layer: 64x64 tile, 32k stages, 1 barrier/stage, 1-term tf32 -------
__global__ __launch_bounds__(256, 4) void fused_layer(
    const float* __restrict__ A, long long strideA,
    const float* __restrict__ muW, const float* __restrict__ vW,
    const float* __restrict__ mub, const float* __restrict__ vb,
    float* __restrict__ C, int K, int N, int relu, int round_out,
    uint32_t wk0, uint32_t wk1, uint32_t bk0, uint32_t bk1, uint32_t one)
{
    const int s    = blockIdx.y;
    const int nblk = blockIdx.x;
    const int t    = threadIdx.x;      // 256

    __shared__ float As[2][32][68];    // [buf][k][m]  (tf32 values)
    __shared__ float Bs[2][32][68];    // [buf][k][n]  (tf32 values)
    __shared__ float bias_s[64];

    const int lr   = t >> 2;           // 0..63 row (A-row / W-row) producer
    const int lk4  = (t & 3) << 2;     // k offset 0,4,8,12 within 16-k half
    const int lane = t & 31;
    const int wrp  = t >> 5;           // 0..7
    const int m0   = (wrp & 3) * 16;
    const int n0b  = (wrp >> 2) * 32;
    const int ka   = lane & 3;
    const int ra   = lane >> 2;

    const float* Ab     = A + (long long)s * strideA;
    const int    n_glob = nblk * 64 + lr;
    const float* muRow  = muW + (long long)n_glob * K;
    const float* vRow   = vW  + (long long)n_glob * K;
    const uint32_t eBase = ((uint32_t)s * (uint32_t)N + (uint32_t)n_glob) * (uint32_t)K;

    if (t < 64) {
        int nb = nblk * 64 + t;
        uint2 r = threefry2x32_dev(bk0, bk1, 0u, (uint32_t)(s * N + nb), one);
        bias_s[t] = __fmaf_rn(__expf(vb[nb]), jax_normal_fast(r.x ^ r.y), mub[nb]);
    }

    const int nst = (K + 31) >> 5;     // 32-k stages (last half-stage zero-padded)

    // ---- prologue: gen stage 0 straight into buf 0 ----
    gen_stage(Ab, muRow, vRow, K, 0, eBase, wk0, wk1, one, As[0], Bs[0], lr, lk4);

    float acc[4][4];
#pragma unroll
    for (int i = 0; i < 4; i++)
#pragma unroll
        for (int j = 0; j < 4; j++) acc[i][j] = 0.0f;

    // ---- main loop: sync | gen(c+1)->buf^1 | MMA(c) from buf ----
    for (int c = 0; c < nst; c++) {
        __syncthreads();
        const int buf = c & 1;

        if (c + 1 < nst) {
            gen_stage(Ab, muRow, vRow, K, (c + 1) << 5, eBase, wk0, wk1, one,
                      As[buf ^ 1], Bs[buf ^ 1], lr, lk4);
        }

        // MMA over stage c: 4 k8-steps x 4 n8-tiles, 1-term (A & B both tf32)
#pragma unroll
        for (int ks = 0; ks < 4; ks++) {
            const int kb = ks * 8;
            uint32_t a0 = __float_as_uint(As[buf][kb + ka    ][m0 + ra    ]);
            uint32_t a1 = __float_as_uint(As[buf][kb + ka    ][m0 + ra + 8]);
            uint32_t a2 = __float_as_uint(As[buf][kb + ka + 4][m0 + ra    ]);
            uint32_t a3 = __float_as_uint(As[buf][kb + ka + 4][m0 + ra + 8]);
#pragma unroll
            for (int tj = 0; tj < 4; tj++) {
                uint32_t b0 = __float_as_uint(Bs[buf][kb + ka    ][n0b + tj * 8 + ra]);
                uint32_t b1 = __float_as_uint(Bs[buf][kb + ka + 4][n0b + tj * 8 + ra]);
                mma_tf32(acc[tj], a0, a1, a2, a3, b0, b1);
            }
        }
    }

    // ---- epilogue: +bias, relu, optional tf32 round, store ----
    const int row0 = m0 + ra;
    const int row1 = m0 + ra + 8;
#pragma unroll
    for (int tj = 0; tj < 4; tj++) {
        int n = n0b + tj * 8 + 2 * ka;
        float bb0 = bias_s[n], bb1 = bias_s[n + 1];
        float v00 = acc[tj][0] + bb0, v01 = acc[tj][1] + bb1;
        float v10 = acc[tj][2] + bb0, v11 = acc[tj][3] + bb1;
        if (relu) {
            v00 = fmaxf(v00, 0.f); v01 = fmaxf(v01, 0.f);
            v10 = fmaxf(v10, 0.f); v11 = fmaxf(v11, 0.f);
        }
        if (round_out) {
            v00 = tf32_round(v00); v01 = tf32_round(v01);
            v10 = tf32_round(v10); v11 = tf32_round(v11);
        }
        float* p0 = C + ((long long)s * 64 + row0) * N + nblk * 64 + n;
        float* p1 = C + ((long long)s * 64 + row1) * N + nblk * 64 + n;
        *(float2*)p0 = make_float2(v00, v01);
        *(float2*)p1 = make_float2(v10, v11);
    }
}

// ---------------- final layer: 2 blocks per sample, gen partitioned by output-half --------
__global__ __launch_bounds__(256) void layer3_fused(
    const float* __restrict__ H,
    const float* __restrict__ muW, const float* __restrict__ vW,
    const float* __restrict__ mub, const float* __restrict__ vb,
    float* __restrict__ out,
    uint32_t wk0, uint32_t wk1, uint32_t bk0, uint32_t bk1, uint32_t one)
{
    const int s = blockIdx.x;
    const int h = blockIdx.y;
    const int t = threadIdx.x;
    __shared__ float Ws[5 * D_H];
    __shared__ float bsm[5];

#pragma unroll
    for (int i = 0; i < (5 * D_H) / 256; i++) {
        int j = t + 256 * i;
        uint32_t e = (uint32_t)(s * (D_OUT * D_H) + h * (5 * D_H) + j);
        uint2 r = threefry2x32_dev(wk0, wk1, 0u, e, one);
        int jg = h * (5 * D_H) + j;
        Ws[j] = __fmaf_rn(__expf(vW[jg]), jax_normal_fast(r.x ^ r.y), muW[jg]);
    }
    if (t < 5) {
        int og = h * 5 + t;
        uint2 r = threefry2x32_dev(bk0, bk1, 0u, (uint32_t)(s * D_OUT + og), one);
        bsm[t] = __fmaf_rn(__expf(vb[og]), jax_normal_fast(r.x ^ r.y), mub[og]);
    }
    __syncthreads();

    const int w = t >> 5, l = t & 31;
#pragma unroll
    for (int ri = 0; ri < 8; ri++) {
        int b = w * 8 + ri;
        const float* Hb = H + ((long long)s * BATCH + b) * D_H;
        float hh[16];
#pragma unroll
        for (int i = 0; i < 16; i++) hh[i] = Hb[l + 32 * i];
#pragma unroll
        for (int o = 0; o < 5; o++) {
            float acc = 0.0f;
#pragma unroll
            for (int i = 0; i < 16; i++)
                acc = __fmaf_rn(hh[i], Ws[o * D_H + l + 32 * i], acc);
            acc += __shfl_xor_sync(0xffffffffu, acc, 16);
            acc += __shfl_xor_sync(0xffffffffu, acc, 8);
            acc += __shfl_xor_sync(0xffffffffu, acc, 4);
            acc += __shfl_xor_sync(0xffffffffu, acc, 2);
            acc += __shfl_xor_sync(0xffffffffu, acc, 1);
            if (l == 0)
                out[((long long)s * BATCH + b) * D_OUT + h * 5 + o] = acc + bsm[o];
        }
    }
}

// ---------------- host-side threefry (subkey derivation) ----------------
static inline uint32_t h_rotl(uint32_t x, int r) { return (x << r) | (x >> (32 - r)); }
static void tf_host(uint32_t k0, uint32_t k1, uint32_t x0, uint32_t x1,
                    uint32_t* o0, uint32_t* o1) {
    uint32_t k2 = k0 ^ k1 ^ 0x1BD11BDAu;
    x0 += k0; x1 += k1;
    static const int R[2][4] = {{13,15,26,6},{17,29,16,24}};
    const uint32_t ks[3] = {k0, k1, k2};
    for (int i = 0; i < 5; i++) {
        for (int r = 0; r < 4; r++) {
            x0 += x1; x1 = h_rotl(x1, R[i & 1][r]); x1 ^= x0;
        }
        x0 += ks[(i + 1) % 3];
        x1 += ks[(i + 2) % 3] + (uint32_t)(i + 1);
    }
    *o0 = x0; *o1 = x1;
}

extern "C" void kernel_launch(void* const* d_in, const int* in_sizes, int n_in,
                              void* d_out, int out_size) {
    const float* x    = (const float*)d_in[0];
    const float* muW0 = (const float*)d_in[1];
    const float* mub0 = (const float*)d_in[2];
    const float* muW1 = (const float*)d_in[3];
    const float* mub1 = (const float*)d_in[4];
    const float* muW2 = (const float*)d_in[5];
    const float* mub2 = (const float*)d_in[6];
    const float* muW3 = (const float*)d_in[7];
    const float* mub3 = (const float*)d_in[8];
    const float* vW0  = (const float*)d_in[9];
    const float* vb0  = (const float*)d_in[10];
    const float* vW1  = (const float*)d_in[11];
    const float* vb1  = (const float*)d_in[12];
    const float* vW2  = (const float*)d_in[13];
    const float* vb2  = (const float*)d_in[14];
    const float* vW3  = (const float*)d_in[15];
    const float* vb3  = (const float*)d_in[16];
    float* out = (float*)d_out;

    uint32_t kk[8][2];
    for (int i = 0; i < 8; i++) tf_host(0u, 1u, 0u, (uint32_t)i, &kk[i][0], &kk[i][1]);

    float *pX, *pH1, *pH2, *pH3;
    cudaGetSymbolAddress((void**)&pX,  g_X);
    cudaGetSymbolAddress((void**)&pH1, g_H1);
    cudaGetSymbolAddress((void**)&pH2, g_H2);
    cudaGetSymbolAddress((void**)&pH3, g_H3);

    const uint32_t one = 1u;   // runtime constant -> forces IMAD in threefry rounds

    round_x<<<(BATCH * D_IN + 255) / 256, 256>>>(x, pX, BATCH * D_IN);

    fused_layer<<<dim3(D_H/64, NSAMP), 256>>>(pX,  0,
                                              muW0, vW0, mub0, vb0,
                                              pH1, D_IN, D_H, 1, 1,
                                              kk[0][0], kk[0][1], kk[1][0], kk[1][1], one);
    fused_layer<<<dim3(D_H/64, NSAMP), 256>>>(pH1, (long long)BATCH*D_H,
                                              muW1, vW1, mub1, vb1,
                                              pH2, D_H, D_H, 1, 1,
                                              kk[2][0], kk[2][1], kk[3][0], kk[3][1], one);
    fused_layer<<<dim3(D_H/64, NSAMP), 256>>>(pH2, (long long)BATCH*D_H,
                                              muW2, vW2, mub2, vb2,
                                              pH3, D_H, D_H, 1, 0,
                                              kk[4][0], kk[4][1], kk[5][0], kk[5][1], one);
    layer3_fused<<<dim3(NSAMP, 2), 256>>>(pH3, muW3, vW3, mub3, vb3, out,
                                          kk[6][0], kk[6][1], kk[7][0], kk[7][1], one);
}